// round 10
// baseline (speedup 1.0000x reference)
#include <cuda_runtime.h>

#define NPTS 300000
#define NBLK 1172   // ceil(NPTS / 256)

// ---------------- scratch (static device globals; no allocation) ----------------
__device__ float g_h[NPTS * 32];                 // bottleneck activations [N,32]
__device__ float g_ms[(size_t)NPTS * 192];       // concat(feat1,feat2,feat3) [N,192]
__device__ float g_pooled[192];                  // global max pool
__device__ float g_wf[192 * 64];                 // attn-scaled fusion weights

// ---------------- packed f32x2 helpers ----------------
__device__ __forceinline__ unsigned long long pack2(float x) {
    unsigned long long r;
    asm("mov.b64 %0, {%1, %1};" : "=l"(r) : "f"(x));
    return r;
}
__device__ __forceinline__ void ffma2(unsigned long long &d,
                                      unsigned long long a,
                                      unsigned long long b) {
    asm("fma.rn.f32x2 %0, %1, %2, %0;" : "+l"(d) : "l"(a), "l"(b));
}
__device__ __forceinline__ float lo32(unsigned long long v) {
    return __uint_as_float((unsigned)(v & 0xffffffffull));
}
__device__ __forceinline__ float hi32(unsigned long long v) {
    return __uint_as_float((unsigned)(v >> 32));
}

// ---------------- zero the pooled max ----------------
__global__ void k_zero() {
    g_pooled[threadIdx.x] = 0.f;
}

// ---------------- h = relu(bn2a(features @ W2a)) : [N,64]@[64,32] ----------------
__global__ __launch_bounds__(256) void k_h(const float* __restrict__ f,
                                           const float* __restrict__ W2a,
                                           const float* __restrict__ s,
                                           const float* __restrict__ b) {
    __shared__ float Ws[64 * 32];
    const int tid = threadIdx.x;
#pragma unroll
    for (int i = 0; i < 8; i++) Ws[i * 256 + tid] = W2a[i * 256 + tid];
    __syncthreads();

    const int p = blockIdx.x * 256 + tid;
    if (p >= NPTS) return;

    unsigned long long acc[16];
#pragma unroll
    for (int i = 0; i < 16; i++) acc[i] = 0ull;

    const float4* fr = (const float4*)(f + p * 64);
#pragma unroll 1
    for (int c4 = 0; c4 < 16; c4++) {
        float4 v = fr[c4];
#pragma unroll
        for (int cc = 0; cc < 4; cc++) {
            unsigned long long g2 = pack2((&v.x)[cc]);
            const ulonglong2* wr = (const ulonglong2*)(Ws + (c4 * 4 + cc) * 32);
#pragma unroll
            for (int d = 0; d < 8; d++) {
                ulonglong2 w = wr[d];
                ffma2(acc[2 * d],     w.x, g2);
                ffma2(acc[2 * d + 1], w.y, g2);
            }
        }
    }
    float* o = g_h + p * 32;
#pragma unroll
    for (int d = 0; d < 16; d++) {
        float r0 = fmaxf(lo32(acc[d]) * s[2 * d]     + b[2 * d],     0.f);
        float r1 = fmaxf(hi32(acc[d]) * s[2 * d + 1] + b[2 * d + 1], 0.f);
        *(float2*)(o + 2 * d) = make_float2(r0, r1);
    }
}

// ---------------- sparse conv path: ms[:,coff:+64] = relu(bn(sum_k gather_k(src)@W[k])) ----
// CTA = 256 threads, 256 points, 1 point/thread (acc = 64 regs, no spills).
// Gathered rows staged into padded SMEM (coalesced), weights double-buffered
// in SMEM (warp-broadcast LDS.128). __launch_bounds__(256,2) caps regs at 128.
template <int CIN>
__global__ __launch_bounds__(256, 2) void k_path(const float* __restrict__ src,
                                                 const int*   __restrict__ nbr,
                                                 const float* __restrict__ W,
                                                 const float* __restrict__ bns,
                                                 const float* __restrict__ bnb,
                                                 int coff) {
    constexpr int GSTR = CIN + 4;            // pad to kill bank conflicts
    extern __shared__ float sm[];
    float* Wb = sm;                          // [2][CIN][64]
    float* G  = sm + 2 * CIN * 64;           // [256][GSTR]

    const int tid = threadIdx.x;
    const int p0  = blockIdx.x * 256;

    unsigned long long acc[32];
#pragma unroll
    for (int i = 0; i < 32; i++) acc[i] = 0ull;

    // stage W[0] into buffer 0 (CIN*64 floats, 256 threads, float4)
    {
        const float4* wsrc = (const float4*)W;
        float4* wdst = (float4*)Wb;
#pragma unroll
        for (int i = 0; i < CIN / 16; i++) wdst[i * 256 + tid] = wsrc[i * 256 + tid];
    }

    for (int k = 0; k < 9; k++) {
        __syncthreads();   // previous compute done (G free), current W staged
        // ---- cooperative gather of 256 rows for this offset k ----
        {
            constexpr int TPR = CIN / 4;       // threads per row (float4 lanes)
            constexpr int RPP = 256 / TPR;     // rows per pass
            const int lane = tid % TPR;
            const int rb   = tid / TPR;
#pragma unroll
            for (int pass = 0; pass < 256 / RPP; pass++) {
                int r = pass * RPP + rb;
                int p = p0 + r;
                int idx = (p < NPTS) ? nbr[k * NPTS + p] : -1;
                float4 v = make_float4(0.f, 0.f, 0.f, 0.f);
                if (idx >= 0) v = *(const float4*)(src + (size_t)idx * CIN + lane * 4);
                *(float4*)(G + r * GSTR + lane * 4) = v;
            }
        }
        // ---- stage next k's weights into the other buffer ----
        if (k < 8) {
            const float4* wsrc = (const float4*)(W + (k + 1) * CIN * 64);
            float4* wdst = (float4*)(Wb + ((k + 1) & 1) * CIN * 64);
#pragma unroll
            for (int i = 0; i < CIN / 16; i++) wdst[i * 256 + tid] = wsrc[i * 256 + tid];
        }
        __syncthreads();
        // ---- compute: 1 point per thread, all 64 outputs ----
        const float* Wk = Wb + (k & 1) * CIN * 64;
        const float* gA = G + tid * GSTR;
#pragma unroll 1
        for (int c4 = 0; c4 < CIN / 4; c4++) {
            float4 a4 = *(const float4*)(gA + c4 * 4);
#pragma unroll
            for (int cc = 0; cc < 4; cc++) {
                unsigned long long a2 = pack2((&a4.x)[cc]);
                const ulonglong2* wr = (const ulonglong2*)(Wk + (c4 * 4 + cc) * 64);
#pragma unroll
                for (int d = 0; d < 16; d++) {
                    ulonglong2 w = wr[d];
                    ffma2(acc[2 * d],     w.x, a2);
                    ffma2(acc[2 * d + 1], w.y, a2);
                }
            }
        }
    }

    // ---- epilogue: bn + relu + store into ms ----
    {
        int p = p0 + tid;
        if (p < NPTS) {
            float* o = g_ms + (size_t)p * 192 + coff;
#pragma unroll
            for (int d = 0; d < 32; d++) {
                float r0 = fmaxf(lo32(acc[d]) * bns[2 * d]     + bnb[2 * d],     0.f);
                float r1 = fmaxf(hi32(acc[d]) * bns[2 * d + 1] + bnb[2 * d + 1], 0.f);
                *(float2*)(o + 2 * d) = make_float2(r0, r1);
            }
        }
    }
}

// ---------------- global max pool over ms (values >= 0 post-ReLU) ----------------
__global__ __launch_bounds__(192) void k_pool() {
    const int c = threadIdx.x;
    float m = 0.f;
    for (int r = blockIdx.x; r < NPTS; r += gridDim.x)
        m = fmaxf(m, g_ms[(size_t)r * 192 + c]);
    atomicMax((int*)&g_pooled[c], __float_as_int(m));   // valid: all values >= 0
}

// ---------------- attention MLP + fold attn into Wf ----------------
// A1_w: [192,16], A1_b: [16], A2_w: [16,192], A2_b: [192]  (bottleneck = COUT/4 = 16)
__global__ __launch_bounds__(192) void k_attn(const float* __restrict__ A1w,
                                              const float* __restrict__ A1b,
                                              const float* __restrict__ A2w,
                                              const float* __restrict__ A2b,
                                              const float* __restrict__ Wf) {
    __shared__ float sp[192], t1[16];
    const int t = threadIdx.x;
    sp[t] = g_pooled[t];
    __syncthreads();
    if (t < 16) {
        float s = A1b[t];
        for (int i = 0; i < 192; i++) s += sp[i] * A1w[i * 16 + t];
        t1[t] = fmaxf(s, 0.f);
    }
    __syncthreads();
    float s = A2b[t];
#pragma unroll
    for (int i = 0; i < 16; i++) s += t1[i] * A2w[i * 192 + t];
    float a = 1.f / (1.f + expf(-s));
    for (int d = 0; d < 64; d++) g_wf[t * 64 + d] = a * Wf[t * 64 + d];
}

// ---------------- fused = relu(bnf((ms * attn) @ Wf)) = relu(bnf(ms @ Wf')) ----------------
__global__ __launch_bounds__(256, 2) void k_fuse(const float* __restrict__ s,
                                                 const float* __restrict__ b,
                                                 float* __restrict__ out) {
    extern __shared__ float Ws[];   // 192*64 scaled fusion weights
    const int tid = threadIdx.x;
#pragma unroll
    for (int i = 0; i < 12; i++)
        ((float4*)Ws)[i * 256 + tid] = ((const float4*)g_wf)[i * 256 + tid];
    __syncthreads();

    const int p = blockIdx.x * 256 + tid;
    if (p >= NPTS) return;

    unsigned long long acc[32];
#pragma unroll
    for (int i = 0; i < 32; i++) acc[i] = 0ull;

    const float4* mr = (const float4*)(g_ms + (size_t)p * 192);
#pragma unroll 1
    for (int c4 = 0; c4 < 48; c4++) {
        float4 v = mr[c4];
#pragma unroll
        for (int cc = 0; cc < 4; cc++) {
            unsigned long long g2 = pack2((&v.x)[cc]);
            const ulonglong2* wr = (const ulonglong2*)(Ws + (c4 * 4 + cc) * 64);
#pragma unroll
            for (int d = 0; d < 16; d++) {
                ulonglong2 w = wr[d];
                ffma2(acc[2 * d],     w.x, g2);
                ffma2(acc[2 * d + 1], w.y, g2);
            }
        }
    }
    float* o = out + (size_t)p * 64;
#pragma unroll
    for (int d = 0; d < 32; d++) {
        float r0 = fmaxf(lo32(acc[d]) * s[2 * d]     + b[2 * d],     0.f);
        float r1 = fmaxf(hi32(acc[d]) * s[2 * d + 1] + b[2 * d + 1], 0.f);
        *(float2*)(o + 2 * d) = make_float2(r0, r1);
    }
}

// ---------------- launch ----------------
extern "C" void kernel_launch(void* const* d_in, const int* in_sizes, int n_in,
                              void* d_out, int out_size) {
    const float* features = (const float*)d_in[0];
    const float* W1    = (const float*)d_in[1];
    const float* bn1s  = (const float*)d_in[2];
    const float* bn1b  = (const float*)d_in[3];
    const float* W2a   = (const float*)d_in[4];
    const float* bn2as = (const float*)d_in[5];
    const float* bn2ab = (const float*)d_in[6];
    const float* W2b   = (const float*)d_in[7];
    const float* bn2bs = (const float*)d_in[8];
    const float* bn2bb = (const float*)d_in[9];
    const float* W3    = (const float*)d_in[10];
    const float* bn3s  = (const float*)d_in[11];
    const float* bn3b  = (const float*)d_in[12];
    const float* A1w   = (const float*)d_in[13];
    const float* A1b   = (const float*)d_in[14];
    const float* A2w   = (const float*)d_in[15];
    const float* A2b   = (const float*)d_in[16];
    const float* Wf    = (const float*)d_in[17];
    const float* bnfs  = (const float*)d_in[18];
    const float* bnfb  = (const float*)d_in[19];
    const int*   nbr1  = (const int*)d_in[20];
    const int*   nbr2  = (const int*)d_in[21];
    float* out = (float*)d_out;

    float* hptr = nullptr;
    cudaGetSymbolAddress((void**)&hptr, g_h);

    const int smem64 = 2 * 64 * 64 * 4 + 256 * 68 * 4;   // 102400
    const int smem32 = 2 * 32 * 64 * 4 + 256 * 36 * 4;   // 53248
    const int smemF  = 192 * 64 * 4;                     // 49152
    cudaFuncSetAttribute(k_path<64>, cudaFuncAttributeMaxDynamicSharedMemorySize, smem64);
    cudaFuncSetAttribute(k_path<32>, cudaFuncAttributeMaxDynamicSharedMemorySize, smem32);
    cudaFuncSetAttribute(k_fuse,     cudaFuncAttributeMaxDynamicSharedMemorySize, smemF);

    k_zero<<<1, 192>>>();
    k_h<<<NBLK, 256>>>(features, W2a, bn2as, bn2ab);
    k_path<64><<<NBLK, 256, smem64>>>(features, nbr1, W1,  bn1s,  bn1b,  0);
    k_path<32><<<NBLK, 256, smem32>>>(hptr,     nbr1, W2b, bn2bs, bn2bb, 64);
    k_path<64><<<NBLK, 256, smem64>>>(features, nbr2, W3,  bn3s,  bn3b,  128);
    k_pool<<<2048, 192>>>();
    k_attn<<<1, 192>>>(A1w, A1b, A2w, A2b, Wf);
    k_fuse<<<NBLK, 256, smemF>>>(bnfs, bnfb, out);
}

// round 11
// speedup vs baseline: 1.1959x; 1.1959x over previous
#include <cuda_runtime.h>

#define NPTS 300000
#define NBLK 1172   // ceil(NPTS / 256)

// ---------------- scratch (static device globals; no allocation) ----------------
__device__ float g_h[NPTS * 32];                 // bottleneck activations [N,32]
__device__ float g_ms[(size_t)NPTS * 192];       // concat(feat1,feat2,feat3) [N,192]
__device__ float g_pooled[192];                  // global max pool
__device__ float g_wf[192 * 64];                 // attn-scaled fusion weights

// ---------------- packed f32x2 helpers ----------------
__device__ __forceinline__ unsigned long long pack2(float x) {
    unsigned long long r;
    asm("mov.b64 %0, {%1, %1};" : "=l"(r) : "f"(x));
    return r;
}
__device__ __forceinline__ void ffma2(unsigned long long &d,
                                      unsigned long long a,
                                      unsigned long long b) {
    asm("fma.rn.f32x2 %0, %1, %2, %0;" : "+l"(d) : "l"(a), "l"(b));
}
__device__ __forceinline__ float lo32(unsigned long long v) {
    return __uint_as_float((unsigned)(v & 0xffffffffull));
}
__device__ __forceinline__ float hi32(unsigned long long v) {
    return __uint_as_float((unsigned)(v >> 32));
}

// ---------------- zero the pooled max ----------------
__global__ void k_zero() {
    g_pooled[threadIdx.x] = 0.f;
}

// ---------------- h = relu(bn2a(features @ W2a)) : [N,64]@[64,32] ----------------
__global__ __launch_bounds__(256) void k_h(const float* __restrict__ f,
                                           const float* __restrict__ W2a,
                                           const float* __restrict__ s,
                                           const float* __restrict__ b) {
    __shared__ float Ws[64 * 32];
    const int tid = threadIdx.x;
#pragma unroll
    for (int i = 0; i < 8; i++) Ws[i * 256 + tid] = W2a[i * 256 + tid];
    __syncthreads();

    const int p = blockIdx.x * 256 + tid;
    if (p >= NPTS) return;

    unsigned long long acc[16];
#pragma unroll
    for (int i = 0; i < 16; i++) acc[i] = 0ull;

    const float4* fr = (const float4*)(f + p * 64);
#pragma unroll 1
    for (int c4 = 0; c4 < 16; c4++) {
        float4 v = fr[c4];
#pragma unroll
        for (int cc = 0; cc < 4; cc++) {
            unsigned long long g2 = pack2((&v.x)[cc]);
            const ulonglong2* wr = (const ulonglong2*)(Ws + (c4 * 4 + cc) * 32);
#pragma unroll
            for (int d = 0; d < 8; d++) {
                ulonglong2 w = wr[d];
                ffma2(acc[2 * d],     w.x, g2);
                ffma2(acc[2 * d + 1], w.y, g2);
            }
        }
    }
    float* o = g_h + p * 32;
#pragma unroll
    for (int d = 0; d < 16; d++) {
        float r0 = fmaxf(lo32(acc[d]) * s[2 * d]     + b[2 * d],     0.f);
        float r1 = fmaxf(hi32(acc[d]) * s[2 * d + 1] + b[2 * d + 1], 0.f);
        *(float2*)(o + 2 * d) = make_float2(r0, r1);
    }
}

// ---------------- sparse conv path: ms[:,coff:+64] = relu(bn(sum_k gather_k(src)@W[k])) ----
// CTA = 256 threads, 256 points. Work split: 2 points x 32 output channels per
// thread (threads 0-127 -> outputs [0,32), threads 128-255 -> [32,64)), so every
// weight LDS feeds 2 points: FFMA2:LDS = 3.8:1 (crossbar no longer co-limiting).
// acc = 64 regs, no spills. Gather staged in padded SMEM, weights double-buffered.
template <int CIN>
__global__ __launch_bounds__(256, 2) void k_path(const float* __restrict__ src,
                                                 const int*   __restrict__ nbr,
                                                 const float* __restrict__ W,
                                                 const float* __restrict__ bns,
                                                 const float* __restrict__ bnb,
                                                 int coff) {
    constexpr int GSTR = CIN + 4;            // pad: conflict-free phases
    extern __shared__ float sm[];
    float* Wb = sm;                          // [2][CIN][64]
    float* G  = sm + 2 * CIN * 64;           // [256][GSTR]

    const int tid   = threadIdx.x;
    const int pid   = tid & 127;
    const int dbase = (tid >> 7) * 32;
    const int p0    = blockIdx.x * 256;

    unsigned long long accA[16], accB[16];
#pragma unroll
    for (int i = 0; i < 16; i++) { accA[i] = 0ull; accB[i] = 0ull; }

    // stage W[0] into buffer 0 (CIN*64 floats, 256 threads, float4)
    {
        const float4* wsrc = (const float4*)W;
        float4* wdst = (float4*)Wb;
#pragma unroll
        for (int i = 0; i < CIN / 16; i++) wdst[i * 256 + tid] = wsrc[i * 256 + tid];
    }

    for (int k = 0; k < 9; k++) {
        __syncthreads();   // previous compute done (G free), current W staged
        // ---- cooperative gather of 256 rows for this offset k ----
        {
            constexpr int TPR = CIN / 4;       // threads per row (float4 lanes)
            constexpr int RPP = 256 / TPR;     // rows per pass
            const int lane = tid % TPR;
            const int rb   = tid / TPR;
#pragma unroll
            for (int pass = 0; pass < 256 / RPP; pass++) {
                int r = pass * RPP + rb;
                int p = p0 + r;
                int idx = (p < NPTS) ? nbr[k * NPTS + p] : -1;
                float4 v = make_float4(0.f, 0.f, 0.f, 0.f);
                if (idx >= 0) v = *(const float4*)(src + (size_t)idx * CIN + lane * 4);
                *(float4*)(G + r * GSTR + lane * 4) = v;
            }
        }
        // ---- stage next k's weights into the other buffer ----
        if (k < 8) {
            const float4* wsrc = (const float4*)(W + (k + 1) * CIN * 64);
            float4* wdst = (float4*)(Wb + ((k + 1) & 1) * CIN * 64);
#pragma unroll
            for (int i = 0; i < CIN / 16; i++) wdst[i * 256 + tid] = wsrc[i * 256 + tid];
        }
        __syncthreads();
        // ---- compute: 2 points x 32 outputs per thread ----
        const float* Wk = Wb + (k & 1) * CIN * 64 + dbase;
        const float* gA = G + pid * GSTR;
        const float* gB = gA + 128 * GSTR;
#pragma unroll 1
        for (int c4 = 0; c4 < CIN / 4; c4++) {
            float4 a4 = *(const float4*)(gA + c4 * 4);
            float4 b4 = *(const float4*)(gB + c4 * 4);
#pragma unroll
            for (int cc = 0; cc < 4; cc++) {
                unsigned long long a2 = pack2((&a4.x)[cc]);
                unsigned long long b2 = pack2((&b4.x)[cc]);
                const ulonglong2* wr = (const ulonglong2*)(Wk + (c4 * 4 + cc) * 64);
#pragma unroll
                for (int d = 0; d < 8; d++) {
                    ulonglong2 w = wr[d];
                    ffma2(accA[2 * d],     w.x, a2);
                    ffma2(accA[2 * d + 1], w.y, a2);
                    ffma2(accB[2 * d],     w.x, b2);
                    ffma2(accB[2 * d + 1], w.y, b2);
                }
            }
        }
    }

    // ---- epilogue: bn + relu + store into ms (32 channels at coff+dbase) ----
    {
        const float* bs = bns + dbase;
        const float* bb = bnb + dbase;
        int pa = p0 + pid;                       // always < NPTS (pid <= 127)
        {
            float* o = g_ms + (size_t)pa * 192 + coff + dbase;
#pragma unroll
            for (int d = 0; d < 16; d++) {
                float r0 = fmaxf(lo32(accA[d]) * bs[2 * d]     + bb[2 * d],     0.f);
                float r1 = fmaxf(hi32(accA[d]) * bs[2 * d + 1] + bb[2 * d + 1], 0.f);
                *(float2*)(o + 2 * d) = make_float2(r0, r1);
            }
        }
        int pb = pa + 128;
        if (pb < NPTS) {
            float* o = g_ms + (size_t)pb * 192 + coff + dbase;
#pragma unroll
            for (int d = 0; d < 16; d++) {
                float r0 = fmaxf(lo32(accB[d]) * bs[2 * d]     + bb[2 * d],     0.f);
                float r1 = fmaxf(hi32(accB[d]) * bs[2 * d + 1] + bb[2 * d + 1], 0.f);
                *(float2*)(o + 2 * d) = make_float2(r0, r1);
            }
        }
    }
}

// ---------------- global max pool over ms (values >= 0 post-ReLU) ----------------
__global__ __launch_bounds__(192) void k_pool() {
    const int c = threadIdx.x;
    float m = 0.f;
    for (int r = blockIdx.x; r < NPTS; r += gridDim.x)
        m = fmaxf(m, g_ms[(size_t)r * 192 + c]);
    atomicMax((int*)&g_pooled[c], __float_as_int(m));   // valid: all values >= 0
}

// ---------------- attention MLP + fold attn into Wf ----------------
// A1_w: [192,16], A1_b: [16], A2_w: [16,192], A2_b: [192]  (bottleneck = COUT/4 = 16)
__global__ __launch_bounds__(192) void k_attn(const float* __restrict__ A1w,
                                              const float* __restrict__ A1b,
                                              const float* __restrict__ A2w,
                                              const float* __restrict__ A2b,
                                              const float* __restrict__ Wf) {
    __shared__ float sp[192], t1[16];
    const int t = threadIdx.x;
    sp[t] = g_pooled[t];
    __syncthreads();
    if (t < 16) {
        float s = A1b[t];
        for (int i = 0; i < 192; i++) s += sp[i] * A1w[i * 16 + t];
        t1[t] = fmaxf(s, 0.f);
    }
    __syncthreads();
    float s = A2b[t];
#pragma unroll
    for (int i = 0; i < 16; i++) s += t1[i] * A2w[i * 192 + t];
    float a = 1.f / (1.f + expf(-s));
    for (int d = 0; d < 64; d++) g_wf[t * 64 + d] = a * Wf[t * 64 + d];
}

// ---------------- fused = relu(bnf(ms @ Wf')) ; 2 points x 32 outputs per thread ----
__global__ __launch_bounds__(256, 2) void k_fuse(const float* __restrict__ s,
                                                 const float* __restrict__ b,
                                                 float* __restrict__ out) {
    extern __shared__ float Ws[];   // 192*64 scaled fusion weights
    const int tid = threadIdx.x;
#pragma unroll
    for (int i = 0; i < 12; i++)
        ((float4*)Ws)[i * 256 + tid] = ((const float4*)g_wf)[i * 256 + tid];
    __syncthreads();

    const int pid   = tid & 127;
    const int dbase = (tid >> 7) * 32;
    const int pA    = blockIdx.x * 256 + pid;          // always < NPTS
    const int pB    = pA + 128;
    const int pBc   = (pB < NPTS) ? pB : 0;            // clamp read, guard store

    unsigned long long accA[16], accB[16];
#pragma unroll
    for (int i = 0; i < 16; i++) { accA[i] = 0ull; accB[i] = 0ull; }

    const float4* mA = (const float4*)(g_ms + (size_t)pA  * 192);
    const float4* mB = (const float4*)(g_ms + (size_t)pBc * 192);
#pragma unroll 1
    for (int c4 = 0; c4 < 48; c4++) {
        float4 va = mA[c4];
        float4 vb = mB[c4];
#pragma unroll
        for (int cc = 0; cc < 4; cc++) {
            unsigned long long a2 = pack2((&va.x)[cc]);
            unsigned long long b2 = pack2((&vb.x)[cc]);
            const ulonglong2* wr = (const ulonglong2*)(Ws + (c4 * 4 + cc) * 64 + dbase);
#pragma unroll
            for (int d = 0; d < 8; d++) {
                ulonglong2 w = wr[d];
                ffma2(accA[2 * d],     w.x, a2);
                ffma2(accA[2 * d + 1], w.y, a2);
                ffma2(accB[2 * d],     w.x, b2);
                ffma2(accB[2 * d + 1], w.y, b2);
            }
        }
    }
    const float* bs = s + dbase;
    const float* bb = b + dbase;
    {
        float* o = out + (size_t)pA * 64 + dbase;
#pragma unroll
        for (int d = 0; d < 16; d++) {
            float r0 = fmaxf(lo32(accA[d]) * bs[2 * d]     + bb[2 * d],     0.f);
            float r1 = fmaxf(hi32(accA[d]) * bs[2 * d + 1] + bb[2 * d + 1], 0.f);
            *(float2*)(o + 2 * d) = make_float2(r0, r1);
        }
    }
    if (pB < NPTS) {
        float* o = out + (size_t)pB * 64 + dbase;
#pragma unroll
        for (int d = 0; d < 16; d++) {
            float r0 = fmaxf(lo32(accB[d]) * bs[2 * d]     + bb[2 * d],     0.f);
            float r1 = fmaxf(hi32(accB[d]) * bs[2 * d + 1] + bb[2 * d + 1], 0.f);
            *(float2*)(o + 2 * d) = make_float2(r0, r1);
        }
    }
}

// ---------------- launch ----------------
extern "C" void kernel_launch(void* const* d_in, const int* in_sizes, int n_in,
                              void* d_out, int out_size) {
    const float* features = (const float*)d_in[0];
    const float* W1    = (const float*)d_in[1];
    const float* bn1s  = (const float*)d_in[2];
    const float* bn1b  = (const float*)d_in[3];
    const float* W2a   = (const float*)d_in[4];
    const float* bn2as = (const float*)d_in[5];
    const float* bn2ab = (const float*)d_in[6];
    const float* W2b   = (const float*)d_in[7];
    const float* bn2bs = (const float*)d_in[8];
    const float* bn2bb = (const float*)d_in[9];
    const float* W3    = (const float*)d_in[10];
    const float* bn3s  = (const float*)d_in[11];
    const float* bn3b  = (const float*)d_in[12];
    const float* A1w   = (const float*)d_in[13];
    const float* A1b   = (const float*)d_in[14];
    const float* A2w   = (const float*)d_in[15];
    const float* A2b   = (const float*)d_in[16];
    const float* Wf    = (const float*)d_in[17];
    const float* bnfs  = (const float*)d_in[18];
    const float* bnfb  = (const float*)d_in[19];
    const int*   nbr1  = (const int*)d_in[20];
    const int*   nbr2  = (const int*)d_in[21];
    float* out = (float*)d_out;

    float* hptr = nullptr;
    cudaGetSymbolAddress((void**)&hptr, g_h);

    const int smem64 = 2 * 64 * 64 * 4 + 256 * 68 * 4;   // 102400
    const int smem32 = 2 * 32 * 64 * 4 + 256 * 36 * 4;   // 53248
    const int smemF  = 192 * 64 * 4;                     // 49152
    cudaFuncSetAttribute(k_path<64>, cudaFuncAttributeMaxDynamicSharedMemorySize, smem64);
    cudaFuncSetAttribute(k_path<32>, cudaFuncAttributeMaxDynamicSharedMemorySize, smem32);
    cudaFuncSetAttribute(k_fuse,     cudaFuncAttributeMaxDynamicSharedMemorySize, smemF);

    k_zero<<<1, 192>>>();
    k_h<<<NBLK, 256>>>(features, W2a, bn2as, bn2ab);
    k_path<64><<<NBLK, 256, smem64>>>(features, nbr1, W1,  bn1s,  bn1b,  0);
    k_path<32><<<NBLK, 256, smem32>>>(hptr,     nbr1, W2b, bn2bs, bn2bb, 64);
    k_path<64><<<NBLK, 256, smem64>>>(features, nbr2, W3,  bn3s,  bn3b,  128);
    k_pool<<<2048, 192>>>();
    k_attn<<<1, 192>>>(A1w, A1b, A2w, A2b, Wf);
    k_fuse<<<NBLK, 256, smemF>>>(bnfs, bnfb, out);
}

// round 14
// speedup vs baseline: 2.1051x; 1.7602x over previous
#include <cuda_runtime.h>
#include <cuda_bf16.h>
#include <cstdint>

#define NPTS 300000
#define NBLK 1172          // ceil(NPTS/256)
#define TILE 256
#define NT   1172          // ceil(NPTS/TILE)

// ---------------- scratch (static device globals; no allocation) ----------------
__device__ float g_ms[(size_t)NPTS * 192];
__device__ float g_pooled[192];
__device__ float g_wf[192 * 64];
__device__ __nv_bfloat16 g_fhi[(size_t)NPTS * 64];
__device__ __nv_bfloat16 g_flo[(size_t)NPTS * 64];
__device__ __nv_bfloat16 g_hhi[(size_t)NPTS * 32];
__device__ __nv_bfloat16 g_hlo[(size_t)NPTS * 32];
// pre-split, transposed ([n][c]), SW128-swizzled weight images, 8KB per [k][hi/lo]
__device__ __nv_bfloat16 g_wimg[3][9][2][4096];

// ---------------- helpers ----------------
__device__ __forceinline__ unsigned SWZ(unsigned x) { return x ^ ((x >> 3) & 0x70); }

__device__ __forceinline__ uint32_t smem_u32(const void* p) {
    uint32_t r;
    asm("{ .reg .u64 t; cvta.to.shared.u64 t, %1; cvt.u32.u64 %0, t; }" : "=r"(r) : "l"(p));
    return r;
}
__device__ __forceinline__ uint32_t pkbf(float hi_e, float lo_e) {   // pack {hi_e|lo_e}
    uint32_t r;
    asm("cvt.rn.bf16x2.f32 %0, %1, %2;" : "=r"(r) : "f"(hi_e), "f"(lo_e));
    return r;
}
__device__ __forceinline__ float ubf_lo(uint32_t u) { return __uint_as_float(u << 16); }
__device__ __forceinline__ float ubf_hi(uint32_t u) { return __uint_as_float(u & 0xffff0000u); }

__device__ __forceinline__ void ldsm4(uint32_t* r, uint32_t addr) {
    asm volatile("ldmatrix.sync.aligned.m8n8.x4.shared.b16 {%0,%1,%2,%3}, [%4];"
        : "=r"(r[0]), "=r"(r[1]), "=r"(r[2]), "=r"(r[3]) : "r"(addr));
}
__device__ __forceinline__ void ldsm2(uint32_t* r, uint32_t addr) {
    asm volatile("ldmatrix.sync.aligned.m8n8.x2.shared.b16 {%0,%1}, [%2];"
        : "=r"(r[0]), "=r"(r[1]) : "r"(addr));
}
__device__ __forceinline__ void mma16816(float* d, const uint32_t* a, const uint32_t* b) {
    asm volatile("mma.sync.aligned.m16n8k16.row.col.f32.bf16.bf16.f32 "
        "{%0,%1,%2,%3}, {%4,%5,%6,%7}, {%8,%9}, {%0,%1,%2,%3};"
        : "+f"(d[0]), "+f"(d[1]), "+f"(d[2]), "+f"(d[3])
        : "r"(a[0]), "r"(a[1]), "r"(a[2]), "r"(a[3]), "r"(b[0]), "r"(b[1]));
}

// ---------------- packed f32x2 (scalar kernels) ----------------
__device__ __forceinline__ unsigned long long pack2(float x) {
    unsigned long long r; asm("mov.b64 %0, {%1, %1};" : "=l"(r) : "f"(x)); return r;
}
__device__ __forceinline__ void ffma2(unsigned long long &d, unsigned long long a, unsigned long long b) {
    asm("fma.rn.f32x2 %0, %1, %2, %0;" : "+l"(d) : "l"(a), "l"(b));
}
__device__ __forceinline__ float lo32(unsigned long long v) { return __uint_as_float((unsigned)(v & 0xffffffffull)); }
__device__ __forceinline__ float hi32(unsigned long long v) { return __uint_as_float((unsigned)(v >> 32)); }

// ---------------- zero pooled ----------------
__global__ void k_zero() { g_pooled[threadIdx.x] = 0.f; }

// ---------------- split features into bf16 hi/lo images ----------------
__global__ __launch_bounds__(256) void k_split(const float* __restrict__ f) {
    const int p = blockIdx.x * 256 + threadIdx.x;
    if (p >= NPTS) return;
    const float4* fr = (const float4*)(f + (size_t)p * 64);
    uint32_t* oh = (uint32_t*)(g_fhi + (size_t)p * 64);
    uint32_t* ol = (uint32_t*)(g_flo + (size_t)p * 64);
#pragma unroll
    for (int i = 0; i < 16; i++) {
        float4 v = fr[i];
        uint32_t h0 = pkbf(v.y, v.x), h1 = pkbf(v.w, v.z);
        float r0 = v.x - ubf_lo(h0), r1 = v.y - ubf_hi(h0);
        float r2 = v.z - ubf_lo(h1), r3 = v.w - ubf_hi(h1);
        oh[2 * i] = h0; oh[2 * i + 1] = h1;
        ol[2 * i] = pkbf(r1, r0); ol[2 * i + 1] = pkbf(r3, r2);
    }
}

// ---------------- weight prep: split + transpose + swizzle into g_wimg ----------------
__global__ void k_wprep(const float* __restrict__ W, int path, int cin) {
    int i = blockIdx.x * 256 + threadIdx.x;
    int total = 9 * 64 * cin;
    if (i >= total) return;
    int k = i / (64 * cin);
    int rem = i % (64 * cin);
    int n = rem / cin;          // output channel (B row)
    int c = rem % cin;          // input channel (K)
    float v = W[(k * cin + c) * 64 + n];
    __nv_bfloat16 hi = __float2bfloat16(v);
    float lof = v - __bfloat162float(hi);
    __nv_bfloat16 lo = __float2bfloat16(lof);
    unsigned off = SWZ((unsigned)(n * 128 + c * 2)) >> 1;
    g_wimg[path][k][0][off] = hi;
    g_wimg[path][k][1][off] = lo;
}

// ---------------- h = relu(bn2a(features @ W2a)), stored as bf16 hi/lo ----------------
__global__ __launch_bounds__(256) void k_h(const float* __restrict__ f,
                                           const float* __restrict__ W2a,
                                           const float* __restrict__ s,
                                           const float* __restrict__ b) {
    __shared__ float Ws[64 * 32];
    const int tid = threadIdx.x;
#pragma unroll
    for (int i = 0; i < 8; i++) Ws[i * 256 + tid] = W2a[i * 256 + tid];
    __syncthreads();
    const int p = blockIdx.x * 256 + tid;
    if (p >= NPTS) return;
    unsigned long long acc[16];
#pragma unroll
    for (int i = 0; i < 16; i++) acc[i] = 0ull;
    const float4* fr = (const float4*)(f + (size_t)p * 64);
#pragma unroll 1
    for (int c4 = 0; c4 < 16; c4++) {
        float4 v = fr[c4];
#pragma unroll
        for (int cc = 0; cc < 4; cc++) {
            unsigned long long g2 = pack2((&v.x)[cc]);
            const ulonglong2* wr = (const ulonglong2*)(Ws + (c4 * 4 + cc) * 32);
#pragma unroll
            for (int d = 0; d < 8; d++) {
                ulonglong2 w = wr[d];
                ffma2(acc[2 * d], w.x, g2);
                ffma2(acc[2 * d + 1], w.y, g2);
            }
        }
    }
    uint32_t* oh = (uint32_t*)(g_hhi + (size_t)p * 32);
    uint32_t* ol = (uint32_t*)(g_hlo + (size_t)p * 32);
#pragma unroll
    for (int d = 0; d < 16; d++) {
        float r0 = fmaxf(lo32(acc[d]) * s[2 * d] + b[2 * d], 0.f);
        float r1 = fmaxf(hi32(acc[d]) * s[2 * d + 1] + b[2 * d + 1], 0.f);
        uint32_t h = pkbf(r1, r0);
        float l0 = r0 - ubf_lo(h), l1 = r1 - ubf_hi(h);
        oh[d] = h;
        ol[d] = pkbf(l1, l0);
    }
}

// ---------------- HMMA sparse conv path ----------------
// Tile = 256 points, 8 warps x m32, N=64. 3-term bf16 split, fp32 reg accum.
// SMEM: AH[256x128B] AL[...] (SW128) + per-offset WH/WL (8KB each) = 80KB -> 2 CTA/SM.
template <int CIN>
__global__ __launch_bounds__(256, 2) void k_path_mma(const __nv_bfloat16* __restrict__ shi,
                                                     const __nv_bfloat16* __restrict__ slo,
                                                     const int*   __restrict__ nbr,
                                                     const float* __restrict__ bns,
                                                     const float* __restrict__ bnb,
                                                     int path, int coff) {
    extern __shared__ unsigned char smraw[];
    const uint32_t sb = smem_u32(smraw);
    const uint32_t sAH = sb, sAL = sb + 32768, sWH = sb + 65536, sWL = sb + 73728;
    const int tid = threadIdx.x;
    const int wid = tid >> 5, lane = tid & 31;
    constexpr int NSTEP = CIN / 16;
    constexpr int SEGS = CIN / 8;           // 16B segments per row
    const int p0 = blockIdx.x * TILE;

    float acc[2][8][4];
#pragma unroll
    for (int i = 0; i < 2; i++)
#pragma unroll
        for (int j = 0; j < 8; j++)
#pragma unroll
            for (int q = 0; q < 4; q++) acc[i][j][q] = 0.f;

    // gather roles: SEGS threads per row
    const int gseg = tid & (SEGS - 1);
    const int grow = tid / SEGS;            // 0 .. 256/SEGS-1
    // A-fragment lane addressing
    const int g = lane >> 3, lr = lane & 7;
    const int arow = (g & 1) * 8 + lr;      // row offset within m16 tile
    const int acolb = (g >> 1) * 16;        // +16B for k upper segment
    // B-fragment lane addressing
    const int bn_ = lane & 7, bsegb = ((lane >> 3) & 1) * 16;

#pragma unroll 1
    for (int k = 0; k < 9; k++) {
        __syncthreads();
        // ---- stage this offset's weights (8KB hi + 8KB lo) ----
        {
            const uint4* wh = (const uint4*)&g_wimg[path][k][0][0];
            const uint4* wl = (const uint4*)&g_wimg[path][k][1][0];
            uint4* dh = (uint4*)(smraw + 65536);
            uint4* dl = (uint4*)(smraw + 73728);
            dh[tid] = wh[tid]; dh[tid + 256] = wh[tid + 256];
            dl[tid] = wl[tid]; dl[tid + 256] = wl[tid + 256];
        }
        // ---- cooperative gather (bf16 rows, pre-split) ----
#pragma unroll
        for (int pass = 0; pass < SEGS; pass++) {
            int r = pass * (256 / SEGS) + grow;
            int p = p0 + r;
            int idx = (p < NPTS) ? __ldg(nbr + (size_t)k * NPTS + p) : -1;
            uint32_t a = SWZ((unsigned)(r * 128 + gseg * 16));
            if (idx >= 0) {
                uint4 vh = *(const uint4*)(shi + (size_t)idx * CIN + gseg * 8);
                uint4 vl = *(const uint4*)(slo + (size_t)idx * CIN + gseg * 8);
                *(uint4*)(smraw + a) = vh;
                *(uint4*)(smraw + 32768 + a) = vl;
            } else {
                uint4 z = make_uint4(0, 0, 0, 0);
                *(uint4*)(smraw + a) = z;
                *(uint4*)(smraw + 32768 + a) = z;
            }
        }
        __syncthreads();
        // ---- compute: per kstep: A frags (hi/lo, 2 mtiles) then 8 n-tiles ----
#pragma unroll
        for (int ks = 0; ks < NSTEP; ks++) {
            uint32_t ah0[4], ah1[4], al0[4], al1[4];
            {
                uint32_t ad0 = SWZ((unsigned)((wid * 32 + arow) * 128 + ks * 32 + acolb));
                uint32_t ad1 = SWZ((unsigned)((wid * 32 + 16 + arow) * 128 + ks * 32 + acolb));
                ldsm4(ah0, sAH + ad0); ldsm4(al0, sAL + ad0);
                ldsm4(ah1, sAH + ad1); ldsm4(al1, sAL + ad1);
            }
#pragma unroll
            for (int nt = 0; nt < 8; nt++) {
                uint32_t bad = SWZ((unsigned)((nt * 8 + bn_) * 128 + ks * 32 + bsegb));
                uint32_t wh[2], wl[2];
                ldsm2(wh, sWH + bad);
                ldsm2(wl, sWL + bad);
                mma16816(acc[0][nt], ah0, wh);
                mma16816(acc[1][nt], ah1, wh);
                mma16816(acc[0][nt], al0, wh);
                mma16816(acc[1][nt], al1, wh);
                mma16816(acc[0][nt], ah0, wl);
                mma16816(acc[1][nt], ah1, wl);
            }
        }
    }

    // ---- epilogue: bn + relu + store to g_ms ----
    const int erow = lane >> 2, ecol = (lane & 3) * 2;
#pragma unroll
    for (int mt = 0; mt < 2; mt++) {
        int pr0 = p0 + wid * 32 + mt * 16 + erow;
#pragma unroll
        for (int nt = 0; nt < 8; nt++) {
            int c = nt * 8 + ecol;
            float s0 = bns[c], s1 = bns[c + 1], b0 = bnb[c], b1 = bnb[c + 1];
            if (pr0 < NPTS) {
                float2 v;
                v.x = fmaxf(acc[mt][nt][0] * s0 + b0, 0.f);
                v.y = fmaxf(acc[mt][nt][1] * s1 + b1, 0.f);
                *(float2*)(g_ms + (size_t)pr0 * 192 + coff + c) = v;
            }
            int pr1 = pr0 + 8;
            if (pr1 < NPTS) {
                float2 v;
                v.x = fmaxf(acc[mt][nt][2] * s0 + b0, 0.f);
                v.y = fmaxf(acc[mt][nt][3] * s1 + b1, 0.f);
                *(float2*)(g_ms + (size_t)pr1 * 192 + coff + c) = v;
            }
        }
    }
}

// ---------------- global max pool ----------------
__global__ __launch_bounds__(192) void k_pool() {
    const int c = threadIdx.x;
    float m = 0.f;
    for (int r = blockIdx.x; r < NPTS; r += gridDim.x)
        m = fmaxf(m, g_ms[(size_t)r * 192 + c]);
    atomicMax((int*)&g_pooled[c], __float_as_int(m));
}

// ---------------- attention MLP (bottleneck 16) + fold into Wf ----------------
__global__ __launch_bounds__(192) void k_attn(const float* __restrict__ A1w,
                                              const float* __restrict__ A1b,
                                              const float* __restrict__ A2w,
                                              const float* __restrict__ A2b,
                                              const float* __restrict__ Wf) {
    __shared__ float sp[192], t1[16];
    const int t = threadIdx.x;
    sp[t] = g_pooled[t];
    __syncthreads();
    if (t < 16) {
        float s = A1b[t];
        for (int i = 0; i < 192; i++) s += sp[i] * A1w[i * 16 + t];
        t1[t] = fmaxf(s, 0.f);
    }
    __syncthreads();
    float s = A2b[t];
#pragma unroll
    for (int i = 0; i < 16; i++) s += t1[i] * A2w[i * 192 + t];
    float a = 1.f / (1.f + expf(-s));
    for (int d = 0; d < 64; d++) g_wf[t * 64 + d] = a * Wf[t * 64 + d];
}

// ---------------- fuse: relu(bnf(ms @ Wf')) ; 2 pts x 32 outputs / thread ----------------
__global__ __launch_bounds__(256, 2) void k_fuse(const float* __restrict__ s,
                                                 const float* __restrict__ b,
                                                 float* __restrict__ out) {
    extern __shared__ float Ws[];
    const int tid = threadIdx.x;
#pragma unroll
    for (int i = 0; i < 12; i++)
        ((float4*)Ws)[i * 256 + tid] = ((const float4*)g_wf)[i * 256 + tid];
    __syncthreads();

    const int pid = tid & 127;
    const int dbase = (tid >> 7) * 32;
    const int pA = blockIdx.x * 256 + pid;
    const int pB = pA + 128;
    const int pBc = (pB < NPTS) ? pB : 0;

    unsigned long long accA[16], accB[16];
#pragma unroll
    for (int i = 0; i < 16; i++) { accA[i] = 0ull; accB[i] = 0ull; }

    const float4* mA = (const float4*)(g_ms + (size_t)pA * 192);
    const float4* mB = (const float4*)(g_ms + (size_t)pBc * 192);
#pragma unroll 1
    for (int c4 = 0; c4 < 48; c4++) {
        float4 va = mA[c4];
        float4 vb = mB[c4];
#pragma unroll
        for (int cc = 0; cc < 4; cc++) {
            unsigned long long a2 = pack2((&va.x)[cc]);
            unsigned long long b2 = pack2((&vb.x)[cc]);
            const ulonglong2* wr = (const ulonglong2*)(Ws + (c4 * 4 + cc) * 64 + dbase);
#pragma unroll
            for (int d = 0; d < 8; d++) {
                ulonglong2 w = wr[d];
                ffma2(accA[2 * d], w.x, a2);
                ffma2(accA[2 * d + 1], w.y, a2);
                ffma2(accB[2 * d], w.x, b2);
                ffma2(accB[2 * d + 1], w.y, b2);
            }
        }
    }
    const float* bs = s + dbase;
    const float* bb = b + dbase;
    {
        float* o = out + (size_t)pA * 64 + dbase;
#pragma unroll
        for (int d = 0; d < 16; d++) {
            float r0 = fmaxf(lo32(accA[d]) * bs[2 * d] + bb[2 * d], 0.f);
            float r1 = fmaxf(hi32(accA[d]) * bs[2 * d + 1] + bb[2 * d + 1], 0.f);
            *(float2*)(o + 2 * d) = make_float2(r0, r1);
        }
    }
    if (pB < NPTS) {
        float* o = out + (size_t)pB * 64 + dbase;
#pragma unroll
        for (int d = 0; d < 16; d++) {
            float r0 = fmaxf(lo32(accB[d]) * bs[2 * d] + bb[2 * d], 0.f);
            float r1 = fmaxf(hi32(accB[d]) * bs[2 * d + 1] + bb[2 * d + 1], 0.f);
            *(float2*)(o + 2 * d) = make_float2(r0, r1);
        }
    }
}

// ---------------- launch ----------------
extern "C" void kernel_launch(void* const* d_in, const int* in_sizes, int n_in,
                              void* d_out, int out_size) {
    const float* features = (const float*)d_in[0];
    const float* W1    = (const float*)d_in[1];
    const float* bn1s  = (const float*)d_in[2];
    const float* bn1b  = (const float*)d_in[3];
    const float* W2a   = (const float*)d_in[4];
    const float* bn2as = (const float*)d_in[5];
    const float* bn2ab = (const float*)d_in[6];
    const float* W2b   = (const float*)d_in[7];
    const float* bn2bs = (const float*)d_in[8];
    const float* bn2bb = (const float*)d_in[9];
    const float* W3    = (const float*)d_in[10];
    const float* bn3s  = (const float*)d_in[11];
    const float* bn3b  = (const float*)d_in[12];
    const float* A1w   = (const float*)d_in[13];
    const float* A1b   = (const float*)d_in[14];
    const float* A2w   = (const float*)d_in[15];
    const float* A2b   = (const float*)d_in[16];
    const float* Wf    = (const float*)d_in[17];
    const float* bnfs  = (const float*)d_in[18];
    const float* bnfb  = (const float*)d_in[19];
    const int*   nbr1  = (const int*)d_in[20];
    const int*   nbr2  = (const int*)d_in[21];
    float* out = (float*)d_out;

    __nv_bfloat16 *fhi = nullptr, *flo = nullptr, *hhi = nullptr, *hlo = nullptr;
    cudaGetSymbolAddress((void**)&fhi, g_fhi);
    cudaGetSymbolAddress((void**)&flo, g_flo);
    cudaGetSymbolAddress((void**)&hhi, g_hhi);
    cudaGetSymbolAddress((void**)&hlo, g_hlo);

    const int SMEMP = 81920;            // AH 32K + AL 32K + WH 8K + WL 8K
    const int smemF = 192 * 64 * 4;
    cudaFuncSetAttribute((const void*)k_path_mma<64>, cudaFuncAttributeMaxDynamicSharedMemorySize, SMEMP);
    cudaFuncSetAttribute((const void*)k_path_mma<32>, cudaFuncAttributeMaxDynamicSharedMemorySize, SMEMP);
    cudaFuncSetAttribute((const void*)k_fuse, cudaFuncAttributeMaxDynamicSharedMemorySize, smemF);

    k_zero<<<1, 192>>>();
    k_split<<<NBLK, 256>>>(features);
    k_wprep<<<144, 256>>>(W1, 0, 64);
    k_wprep<<<72, 256>>>(W2b, 1, 32);
    k_wprep<<<144, 256>>>(W3, 2, 64);
    k_h<<<NBLK, 256>>>(features, W2a, bn2as, bn2ab);
    k_path_mma<64><<<NT, 256, SMEMP>>>(fhi, flo, nbr1, bn1s, bn1b, 0, 0);
    k_path_mma<32><<<NT, 256, SMEMP>>>(hhi, hlo, nbr1, bn2bs, bn2bb, 1, 64);
    k_path_mma<64><<<NT, 256, SMEMP>>>(fhi, flo, nbr2, bn3s, bn3b, 2, 128);
    k_pool<<<2048, 192>>>();
    k_attn<<<1, 192>>>(A1w, A1b, A2w, A2b, Wf);
    k_fuse<<<NBLK, 256, smemF>>>(bnfs, bnfb, out);
}

// round 15
// speedup vs baseline: 2.2851x; 1.0855x over previous
#include <cuda_runtime.h>
#include <cuda_bf16.h>
#include <cstdint>

#define NPTS 300000
#define NBLK 1172          // ceil(NPTS/256)
#define TILE 256
#define NT   1172          // ceil(NPTS/TILE)

// ---------------- scratch (static device globals; no allocation) ----------------
__device__ float g_pooled[192];
__device__ __nv_bfloat16 g_mshi[(size_t)NPTS * 192];
__device__ __nv_bfloat16 g_mslo[(size_t)NPTS * 192];
__device__ __nv_bfloat16 g_fhi[(size_t)NPTS * 64];
__device__ __nv_bfloat16 g_flo[(size_t)NPTS * 64];
__device__ __nv_bfloat16 g_hhi[(size_t)NPTS * 32];
__device__ __nv_bfloat16 g_hlo[(size_t)NPTS * 32];
// path weights: pre-split, transposed ([n][c]), SW128-swizzled, 8KB per [k][hi/lo]
__device__ __nv_bfloat16 g_wimg[3][9][2][4096];
// fusion weights (attn-folded): [hi/lo][3 kblocks][64n x 64c swizzled]
__device__ __nv_bfloat16 g_wfimg[2][3][4096];

// ---------------- helpers ----------------
__device__ __forceinline__ unsigned SWZ(unsigned x) { return x ^ ((x >> 3) & 0x70); }

__device__ __forceinline__ uint32_t smem_u32(const void* p) {
    uint32_t r;
    asm("{ .reg .u64 t; cvta.to.shared.u64 t, %1; cvt.u32.u64 %0, t; }" : "=r"(r) : "l"(p));
    return r;
}
__device__ __forceinline__ uint32_t pkbf(float hi_e, float lo_e) {   // pack {hi_e|lo_e}
    uint32_t r;
    asm("cvt.rn.bf16x2.f32 %0, %1, %2;" : "=r"(r) : "f"(hi_e), "f"(lo_e));
    return r;
}
__device__ __forceinline__ float ubf_lo(uint32_t u) { return __uint_as_float(u << 16); }
__device__ __forceinline__ float ubf_hi(uint32_t u) { return __uint_as_float(u & 0xffff0000u); }

__device__ __forceinline__ void ldsm4(uint32_t* r, uint32_t addr) {
    asm volatile("ldmatrix.sync.aligned.m8n8.x4.shared.b16 {%0,%1,%2,%3}, [%4];"
        : "=r"(r[0]), "=r"(r[1]), "=r"(r[2]), "=r"(r[3]) : "r"(addr));
}
__device__ __forceinline__ void ldsm2(uint32_t* r, uint32_t addr) {
    asm volatile("ldmatrix.sync.aligned.m8n8.x2.shared.b16 {%0,%1}, [%2];"
        : "=r"(r[0]), "=r"(r[1]) : "r"(addr));
}
__device__ __forceinline__ void mma16816(float* d, const uint32_t* a, const uint32_t* b) {
    asm volatile("mma.sync.aligned.m16n8k16.row.col.f32.bf16.bf16.f32 "
        "{%0,%1,%2,%3}, {%4,%5,%6,%7}, {%8,%9}, {%0,%1,%2,%3};"
        : "+f"(d[0]), "+f"(d[1]), "+f"(d[2]), "+f"(d[3])
        : "r"(a[0]), "r"(a[1]), "r"(a[2]), "r"(a[3]), "r"(b[0]), "r"(b[1]));
}

// ---------------- packed f32x2 (scalar kernels) ----------------
__device__ __forceinline__ unsigned long long pack2(float x) {
    unsigned long long r; asm("mov.b64 %0, {%1, %1};" : "=l"(r) : "f"(x)); return r;
}
__device__ __forceinline__ void ffma2(unsigned long long &d, unsigned long long a, unsigned long long b) {
    asm("fma.rn.f32x2 %0, %1, %2, %0;" : "+l"(d) : "l"(a), "l"(b));
}
__device__ __forceinline__ float lo32(unsigned long long v) { return __uint_as_float((unsigned)(v & 0xffffffffull)); }
__device__ __forceinline__ float hi32(unsigned long long v) { return __uint_as_float((unsigned)(v >> 32)); }

// ---------------- zero pooled ----------------
__global__ void k_zero() { g_pooled[threadIdx.x] = 0.f; }

// ---------------- split features into bf16 hi/lo images ----------------
__global__ __launch_bounds__(256) void k_split(const float* __restrict__ f) {
    const int p = blockIdx.x * 256 + threadIdx.x;
    if (p >= NPTS) return;
    const float4* fr = (const float4*)(f + (size_t)p * 64);
    uint32_t* oh = (uint32_t*)(g_fhi + (size_t)p * 64);
    uint32_t* ol = (uint32_t*)(g_flo + (size_t)p * 64);
#pragma unroll
    for (int i = 0; i < 16; i++) {
        float4 v = fr[i];
        uint32_t h0 = pkbf(v.y, v.x), h1 = pkbf(v.w, v.z);
        float r0 = v.x - ubf_lo(h0), r1 = v.y - ubf_hi(h0);
        float r2 = v.z - ubf_lo(h1), r3 = v.w - ubf_hi(h1);
        oh[2 * i] = h0; oh[2 * i + 1] = h1;
        ol[2 * i] = pkbf(r1, r0); ol[2 * i + 1] = pkbf(r3, r2);
    }
}

// ---------------- weight prep: split + transpose + swizzle into g_wimg ----------------
__global__ void k_wprep(const float* __restrict__ W, int path, int cin) {
    int i = blockIdx.x * 256 + threadIdx.x;
    int total = 9 * 64 * cin;
    if (i >= total) return;
    int k = i / (64 * cin);
    int rem = i % (64 * cin);
    int n = rem / cin;          // output channel (B row)
    int c = rem % cin;          // input channel (K)
    float v = W[(k * cin + c) * 64 + n];
    __nv_bfloat16 hi = __float2bfloat16(v);
    float lof = v - __bfloat162float(hi);
    __nv_bfloat16 lo = __float2bfloat16(lof);
    unsigned off = SWZ((unsigned)(n * 128 + c * 2)) >> 1;
    g_wimg[path][k][0][off] = hi;
    g_wimg[path][k][1][off] = lo;
}

// ---------------- h = relu(bn2a(features @ W2a)), stored as bf16 hi/lo ----------------
__global__ __launch_bounds__(256) void k_h(const float* __restrict__ f,
                                           const float* __restrict__ W2a,
                                           const float* __restrict__ s,
                                           const float* __restrict__ b) {
    __shared__ float Ws[64 * 32];
    const int tid = threadIdx.x;
#pragma unroll
    for (int i = 0; i < 8; i++) Ws[i * 256 + tid] = W2a[i * 256 + tid];
    __syncthreads();
    const int p = blockIdx.x * 256 + tid;
    if (p >= NPTS) return;
    unsigned long long acc[16];
#pragma unroll
    for (int i = 0; i < 16; i++) acc[i] = 0ull;
    const float4* fr = (const float4*)(f + (size_t)p * 64);
#pragma unroll 1
    for (int c4 = 0; c4 < 16; c4++) {
        float4 v = fr[c4];
#pragma unroll
        for (int cc = 0; cc < 4; cc++) {
            unsigned long long g2 = pack2((&v.x)[cc]);
            const ulonglong2* wr = (const ulonglong2*)(Ws + (c4 * 4 + cc) * 32);
#pragma unroll
            for (int d = 0; d < 8; d++) {
                ulonglong2 w = wr[d];
                ffma2(acc[2 * d], w.x, g2);
                ffma2(acc[2 * d + 1], w.y, g2);
            }
        }
    }
    uint32_t* oh = (uint32_t*)(g_hhi + (size_t)p * 32);
    uint32_t* ol = (uint32_t*)(g_hlo + (size_t)p * 32);
#pragma unroll
    for (int d = 0; d < 16; d++) {
        float r0 = fmaxf(lo32(acc[d]) * s[2 * d] + b[2 * d], 0.f);
        float r1 = fmaxf(hi32(acc[d]) * s[2 * d + 1] + b[2 * d + 1], 0.f);
        uint32_t h = pkbf(r1, r0);
        float l0 = r0 - ubf_lo(h), l1 = r1 - ubf_hi(h);
        oh[d] = h;
        ol[d] = pkbf(l1, l0);
    }
}

// ---------------- HMMA sparse conv path (epilogue -> bf16 hi/lo ms) ----------------
template <int CIN>
__global__ __launch_bounds__(256, 2) void k_path_mma(const __nv_bfloat16* __restrict__ shi,
                                                     const __nv_bfloat16* __restrict__ slo,
                                                     const int*   __restrict__ nbr,
                                                     const float* __restrict__ bns,
                                                     const float* __restrict__ bnb,
                                                     int path, int coff) {
    extern __shared__ unsigned char smraw[];
    const uint32_t sb = smem_u32(smraw);
    const uint32_t sAH = sb, sAL = sb + 32768, sWH = sb + 65536, sWL = sb + 73728;
    const int tid = threadIdx.x;
    const int wid = tid >> 5, lane = tid & 31;
    constexpr int NSTEP = CIN / 16;
    constexpr int SEGS = CIN / 8;
    const int p0 = blockIdx.x * TILE;

    float acc[2][8][4];
#pragma unroll
    for (int i = 0; i < 2; i++)
#pragma unroll
        for (int j = 0; j < 8; j++)
#pragma unroll
            for (int q = 0; q < 4; q++) acc[i][j][q] = 0.f;

    const int gseg = tid & (SEGS - 1);
    const int grow = tid / SEGS;
    const int g = lane >> 3, lr = lane & 7;
    const int arow = (g & 1) * 8 + lr;
    const int acolb = (g >> 1) * 16;
    const int bn_ = lane & 7, bsegb = ((lane >> 3) & 1) * 16;

#pragma unroll 1
    for (int k = 0; k < 9; k++) {
        __syncthreads();
        {
            const uint4* wh = (const uint4*)&g_wimg[path][k][0][0];
            const uint4* wl = (const uint4*)&g_wimg[path][k][1][0];
            uint4* dh = (uint4*)(smraw + 65536);
            uint4* dl = (uint4*)(smraw + 73728);
            dh[tid] = wh[tid]; dh[tid + 256] = wh[tid + 256];
            dl[tid] = wl[tid]; dl[tid + 256] = wl[tid + 256];
        }
#pragma unroll
        for (int pass = 0; pass < SEGS; pass++) {
            int r = pass * (256 / SEGS) + grow;
            int p = p0 + r;
            int idx = (p < NPTS) ? __ldg(nbr + (size_t)k * NPTS + p) : -1;
            uint32_t a = SWZ((unsigned)(r * 128 + gseg * 16));
            if (idx >= 0) {
                uint4 vh = *(const uint4*)(shi + (size_t)idx * CIN + gseg * 8);
                uint4 vl = *(const uint4*)(slo + (size_t)idx * CIN + gseg * 8);
                *(uint4*)(smraw + a) = vh;
                *(uint4*)(smraw + 32768 + a) = vl;
            } else {
                uint4 z = make_uint4(0, 0, 0, 0);
                *(uint4*)(smraw + a) = z;
                *(uint4*)(smraw + 32768 + a) = z;
            }
        }
        __syncthreads();
#pragma unroll
        for (int ks = 0; ks < NSTEP; ks++) {
            uint32_t ah0[4], ah1[4], al0[4], al1[4];
            {
                uint32_t ad0 = SWZ((unsigned)((wid * 32 + arow) * 128 + ks * 32 + acolb));
                uint32_t ad1 = SWZ((unsigned)((wid * 32 + 16 + arow) * 128 + ks * 32 + acolb));
                ldsm4(ah0, sAH + ad0); ldsm4(al0, sAL + ad0);
                ldsm4(ah1, sAH + ad1); ldsm4(al1, sAL + ad1);
            }
#pragma unroll
            for (int nt = 0; nt < 8; nt++) {
                uint32_t bad = SWZ((unsigned)((nt * 8 + bn_) * 128 + ks * 32 + bsegb));
                uint32_t wh[2], wl[2];
                ldsm2(wh, sWH + bad);
                ldsm2(wl, sWL + bad);
                mma16816(acc[0][nt], ah0, wh);
                mma16816(acc[1][nt], ah1, wh);
                mma16816(acc[0][nt], al0, wh);
                mma16816(acc[1][nt], al1, wh);
                mma16816(acc[0][nt], ah0, wl);
                mma16816(acc[1][nt], ah1, wl);
            }
        }
    }

    // epilogue: bn + relu, split to bf16 hi/lo, store
    const int erow = lane >> 2, ecol = (lane & 3) * 2;
#pragma unroll
    for (int mt = 0; mt < 2; mt++) {
#pragma unroll
        for (int half = 0; half < 2; half++) {
            int pr = p0 + wid * 32 + mt * 16 + half * 8 + erow;
            if (pr >= NPTS) continue;
            uint32_t* oh = (uint32_t*)(g_mshi + (size_t)pr * 192 + coff);
            uint32_t* ol = (uint32_t*)(g_mslo + (size_t)pr * 192 + coff);
#pragma unroll
            for (int nt = 0; nt < 8; nt++) {
                int c = nt * 8 + ecol;
                float v0 = fmaxf(acc[mt][nt][2 * half]     * bns[c]     + bnb[c],     0.f);
                float v1 = fmaxf(acc[mt][nt][2 * half + 1] * bns[c + 1] + bnb[c + 1], 0.f);
                uint32_t h = pkbf(v1, v0);
                float l0 = v0 - ubf_lo(h), l1 = v1 - ubf_hi(h);
                oh[c >> 1] = h;
                ol[c >> 1] = pkbf(l1, l0);
            }
        }
    }
}

// ---------------- global max pool over ms (hi+lo) ----------------
__global__ __launch_bounds__(192) void k_pool() {
    const int c = threadIdx.x;
    float m = 0.f;
    for (int r = blockIdx.x; r < NPTS; r += gridDim.x) {
        float v = __bfloat162float(g_mshi[(size_t)r * 192 + c]) +
                  __bfloat162float(g_mslo[(size_t)r * 192 + c]);
        m = fmaxf(m, v);
    }
    atomicMax((int*)&g_pooled[c], __float_as_int(m));
}

// ---------------- attention MLP + fold into Wf + emit split/transposed/swizzled images ----
__global__ __launch_bounds__(192) void k_attn(const float* __restrict__ A1w,
                                              const float* __restrict__ A1b,
                                              const float* __restrict__ A2w,
                                              const float* __restrict__ A2b,
                                              const float* __restrict__ Wf) {
    __shared__ float sp[192], t1[16];
    const int t = threadIdx.x;
    sp[t] = g_pooled[t];
    __syncthreads();
    if (t < 16) {
        float s = A1b[t];
        for (int i = 0; i < 192; i++) s += sp[i] * A1w[i * 16 + t];
        t1[t] = fmaxf(s, 0.f);
    }
    __syncthreads();
    float s = A2b[t];
#pragma unroll
    for (int i = 0; i < 16; i++) s += t1[i] * A2w[i * 192 + t];
    float a = 1.f / (1.f + expf(-s));
    const int kb = t >> 6, cc = t & 63;
    for (int n = 0; n < 64; n++) {
        float v = a * Wf[t * 64 + n];
        __nv_bfloat16 hi = __float2bfloat16(v);
        float lof = v - __bfloat162float(hi);
        unsigned off = SWZ((unsigned)(n * 128 + cc * 2)) >> 1;
        g_wfimg[0][kb][off] = hi;
        g_wfimg[1][kb][off] = __float2bfloat16(lof);
    }
}

// ---------------- HMMA fusion: out = relu(bnf(ms @ Wf')) ----------------
// Tile 256 pts, 8 warps x m32, N=64, K=192 in 3 blocks of 64. 3-term bf16.
// SMEM: AH 32K + AL 32K + WH 24K + WL 24K = 112K -> 2 CTA/SM.
__global__ __launch_bounds__(256, 2) void k_fuse_mma(const float* __restrict__ s,
                                                     const float* __restrict__ b,
                                                     float* __restrict__ out) {
    extern __shared__ unsigned char smraw[];
    const uint32_t sb = smem_u32(smraw);
    const uint32_t sAH = sb, sAL = sb + 32768, sWH = sb + 65536, sWL = sb + 90112;
    const int tid = threadIdx.x;
    const int wid = tid >> 5, lane = tid & 31;
    const int p0 = blockIdx.x * TILE;

    // stage all fusion weights once (24KB hi + 24KB lo)
    {
        const uint4* wh = (const uint4*)&g_wfimg[0][0][0];
        const uint4* wl = (const uint4*)&g_wfimg[1][0][0];
        uint4* dh = (uint4*)(smraw + 65536);
        uint4* dl = (uint4*)(smraw + 90112);
#pragma unroll
        for (int i = 0; i < 6; i++) {
            dh[i * 256 + tid] = wh[i * 256 + tid];
            dl[i * 256 + tid] = wl[i * 256 + tid];
        }
    }

    float acc[2][8][4];
#pragma unroll
    for (int i = 0; i < 2; i++)
#pragma unroll
        for (int j = 0; j < 8; j++)
#pragma unroll
            for (int q = 0; q < 4; q++) acc[i][j][q] = 0.f;

    const int gseg = tid & 7, grow = tid >> 3;       // 8 segs/row, 32 rows/pass
    const int g = lane >> 3, lr = lane & 7;
    const int arow = (g & 1) * 8 + lr;
    const int acolb = (g >> 1) * 16;
    const int bn_ = lane & 7, bsegb = ((lane >> 3) & 1) * 16;

#pragma unroll 1
    for (int kb = 0; kb < 3; kb++) {
        __syncthreads();
        // load A chunk: cols [kb*64, kb*64+64) of ms hi/lo (direct coalesced rows)
#pragma unroll
        for (int pass = 0; pass < 8; pass++) {
            int r = pass * 32 + grow;
            int p = p0 + r;
            uint32_t a = SWZ((unsigned)(r * 128 + gseg * 16));
            if (p < NPTS) {
                uint4 vh = *(const uint4*)(g_mshi + (size_t)p * 192 + kb * 64 + gseg * 8);
                uint4 vl = *(const uint4*)(g_mslo + (size_t)p * 192 + kb * 64 + gseg * 8);
                *(uint4*)(smraw + a) = vh;
                *(uint4*)(smraw + 32768 + a) = vl;
            } else {
                uint4 z = make_uint4(0, 0, 0, 0);
                *(uint4*)(smraw + a) = z;
                *(uint4*)(smraw + 32768 + a) = z;
            }
        }
        __syncthreads();
#pragma unroll
        for (int ks = 0; ks < 4; ks++) {
            uint32_t ah0[4], ah1[4], al0[4], al1[4];
            {
                uint32_t ad0 = SWZ((unsigned)((wid * 32 + arow) * 128 + ks * 32 + acolb));
                uint32_t ad1 = SWZ((unsigned)((wid * 32 + 16 + arow) * 128 + ks * 32 + acolb));
                ldsm4(ah0, sAH + ad0); ldsm4(al0, sAL + ad0);
                ldsm4(ah1, sAH + ad1); ldsm4(al1, sAL + ad1);
            }
#pragma unroll
            for (int nt = 0; nt < 8; nt++) {
                uint32_t bad = SWZ((unsigned)((nt * 8 + bn_) * 128 + ks * 32 + bsegb));
                uint32_t wh[2], wl[2];
                ldsm2(wh, sWH + kb * 8192 + bad);
                ldsm2(wl, sWL + kb * 8192 + bad);
                mma16816(acc[0][nt], ah0, wh);
                mma16816(acc[1][nt], ah1, wh);
                mma16816(acc[0][nt], al0, wh);
                mma16816(acc[1][nt], al1, wh);
                mma16816(acc[0][nt], ah0, wl);
                mma16816(acc[1][nt], ah1, wl);
            }
        }
    }

    // epilogue: bn + relu + fp32 store to out
    const int erow = lane >> 2, ecol = (lane & 3) * 2;
#pragma unroll
    for (int mt = 0; mt < 2; mt++) {
#pragma unroll
        for (int half = 0; half < 2; half++) {
            int pr = p0 + wid * 32 + mt * 16 + half * 8 + erow;
            if (pr >= NPTS) continue;
            float* o = out + (size_t)pr * 64;
#pragma unroll
            for (int nt = 0; nt < 8; nt++) {
                int c = nt * 8 + ecol;
                float2 v;
                v.x = fmaxf(acc[mt][nt][2 * half]     * s[c]     + b[c],     0.f);
                v.y = fmaxf(acc[mt][nt][2 * half + 1] * s[c + 1] + b[c + 1], 0.f);
                *(float2*)(o + c) = v;
            }
        }
    }
}

// ---------------- launch ----------------
extern "C" void kernel_launch(void* const* d_in, const int* in_sizes, int n_in,
                              void* d_out, int out_size) {
    const float* features = (const float*)d_in[0];
    const float* W1    = (const float*)d_in[1];
    const float* bn1s  = (const float*)d_in[2];
    const float* bn1b  = (const float*)d_in[3];
    const float* W2a   = (const float*)d_in[4];
    const float* bn2as = (const float*)d_in[5];
    const float* bn2ab = (const float*)d_in[6];
    const float* W2b   = (const float*)d_in[7];
    const float* bn2bs = (const float*)d_in[8];
    const float* bn2bb = (const float*)d_in[9];
    const float* W3    = (const float*)d_in[10];
    const float* bn3s  = (const float*)d_in[11];
    const float* bn3b  = (const float*)d_in[12];
    const float* A1w   = (const float*)d_in[13];
    const float* A1b   = (const float*)d_in[14];
    const float* A2w   = (const float*)d_in[15];
    const float* A2b   = (const float*)d_in[16];
    const float* Wf    = (const float*)d_in[17];
    const float* bnfs  = (const float*)d_in[18];
    const float* bnfb  = (const float*)d_in[19];
    const int*   nbr1  = (const int*)d_in[20];
    const int*   nbr2  = (const int*)d_in[21];
    float* out = (float*)d_out;

    __nv_bfloat16 *fhi = nullptr, *flo = nullptr, *hhi = nullptr, *hlo = nullptr;
    cudaGetSymbolAddress((void**)&fhi, g_fhi);
    cudaGetSymbolAddress((void**)&flo, g_flo);
    cudaGetSymbolAddress((void**)&hhi, g_hhi);
    cudaGetSymbolAddress((void**)&hlo, g_hlo);

    const int SMEMP  = 81920;            // AH 32K + AL 32K + WH 8K + WL 8K
    const int SMEMF2 = 114688;           // AH 32K + AL 32K + WH 24K + WL 24K
    cudaFuncSetAttribute((const void*)k_path_mma<64>, cudaFuncAttributeMaxDynamicSharedMemorySize, SMEMP);
    cudaFuncSetAttribute((const void*)k_path_mma<32>, cudaFuncAttributeMaxDynamicSharedMemorySize, SMEMP);
    cudaFuncSetAttribute((const void*)k_fuse_mma,     cudaFuncAttributeMaxDynamicSharedMemorySize, SMEMF2);

    k_zero<<<1, 192>>>();
    k_split<<<NBLK, 256>>>(features);
    k_wprep<<<144, 256>>>(W1, 0, 64);
    k_wprep<<<72, 256>>>(W2b, 1, 32);
    k_wprep<<<144, 256>>>(W3, 2, 64);
    k_h<<<NBLK, 256>>>(features, W2a, bn2as, bn2ab);
    k_path_mma<64><<<NT, 256, SMEMP>>>(fhi, flo, nbr1, bn1s, bn1b, 0, 0);
    k_path_mma<32><<<NT, 256, SMEMP>>>(hhi, hlo, nbr1, bn2bs, bn2bb, 1, 64);
    k_path_mma<64><<<NT, 256, SMEMP>>>(fhi, flo, nbr2, bn3s, bn3b, 2, 128);
    k_pool<<<2048, 192>>>();
    k_attn<<<1, 192>>>(A1w, A1b, A2w, A2b, Wf);
    k_fuse_mma<<<NT, 256, SMEMF2>>>(bnfs, bnfb, out);
}

// round 17
// speedup vs baseline: 3.0703x; 1.3436x over previous
#include <cuda_runtime.h>
#include <cuda_bf16.h>
#include <cstdint>

#define NPTS 300000
#define NBLK 1172          // ceil(NPTS/256)
#define TILE 256
#define NT   1172          // ceil(NPTS/TILE)

// ---------------- scratch (static device globals; no allocation) ----------------
__device__ float g_pooled[192];
__device__ __nv_bfloat16 g_mshi[(size_t)NPTS * 192];
__device__ __nv_bfloat16 g_mslo[(size_t)NPTS * 192];
__device__ __nv_bfloat16 g_fhi[(size_t)NPTS * 64];
__device__ __nv_bfloat16 g_flo[(size_t)NPTS * 64];
__device__ __nv_bfloat16 g_hhi[(size_t)NPTS * 32];
__device__ __nv_bfloat16 g_hlo[(size_t)NPTS * 32];
// path weights: pre-split, transposed ([n][c]), SW128-swizzled, 8KB per [k][hi/lo]
__device__ __nv_bfloat16 g_wimg[3][9][2][4096];
// W2a image: [hi/lo][32n x 64c swizzled] (4KB each)
__device__ __nv_bfloat16 g_w2aimg[2][2048];
// fusion weights (attn-folded): [hi/lo][3 kblocks][64n x 64c swizzled]
__device__ __nv_bfloat16 g_wfimg[2][3][4096];

// ---------------- helpers ----------------
__device__ __forceinline__ unsigned SWZ(unsigned x) { return x ^ ((x >> 3) & 0x70); }

__device__ __forceinline__ uint32_t smem_u32(const void* p) {
    uint32_t r;
    asm("{ .reg .u64 t; cvta.to.shared.u64 t, %1; cvt.u32.u64 %0, t; }" : "=r"(r) : "l"(p));
    return r;
}
__device__ __forceinline__ uint32_t pkbf(float hi_e, float lo_e) {   // pack {hi_e|lo_e}
    uint32_t r;
    asm("cvt.rn.bf16x2.f32 %0, %1, %2;" : "=r"(r) : "f"(hi_e), "f"(lo_e));
    return r;
}
__device__ __forceinline__ float ubf_lo(uint32_t u) { return __uint_as_float(u << 16); }
__device__ __forceinline__ float ubf_hi(uint32_t u) { return __uint_as_float(u & 0xffff0000u); }

__device__ __forceinline__ void ldsm4(uint32_t* r, uint32_t addr) {
    asm volatile("ldmatrix.sync.aligned.m8n8.x4.shared.b16 {%0,%1,%2,%3}, [%4];"
        : "=r"(r[0]), "=r"(r[1]), "=r"(r[2]), "=r"(r[3]) : "r"(addr));
}
__device__ __forceinline__ void ldsm2(uint32_t* r, uint32_t addr) {
    asm volatile("ldmatrix.sync.aligned.m8n8.x2.shared.b16 {%0,%1}, [%2];"
        : "=r"(r[0]), "=r"(r[1]) : "r"(addr));
}
__device__ __forceinline__ void mma16816(float* d, const uint32_t* a, const uint32_t* b) {
    asm volatile("mma.sync.aligned.m16n8k16.row.col.f32.bf16.bf16.f32 "
        "{%0,%1,%2,%3}, {%4,%5,%6,%7}, {%8,%9}, {%0,%1,%2,%3};"
        : "+f"(d[0]), "+f"(d[1]), "+f"(d[2]), "+f"(d[3])
        : "r"(a[0]), "r"(a[1]), "r"(a[2]), "r"(a[3]), "r"(b[0]), "r"(b[1]));
}
__device__ __forceinline__ void cpa16(uint32_t dst, const void* src, uint32_t ss) {
    asm volatile("cp.async.ca.shared.global [%0], [%1], 16, %2;"
        :: "r"(dst), "l"(src), "r"(ss) : "memory");
}
#define CP_COMMIT() asm volatile("cp.async.commit_group;" ::: "memory")
#define CP_WAIT0()  asm volatile("cp.async.wait_group 0;" ::: "memory")
#define CP_WAIT1()  asm volatile("cp.async.wait_group 1;" ::: "memory")

// ---------------- packed f32x2 ----------------
__device__ __forceinline__ unsigned long long pack2(float x) {
    unsigned long long r; asm("mov.b64 %0, {%1, %1};" : "=l"(r) : "f"(x)); return r;
}

// ---------------- zero pooled ----------------
__global__ void k_zero() { g_pooled[threadIdx.x] = 0.f; }

// ---------------- split features into bf16 hi/lo images ----------------
__global__ __launch_bounds__(256) void k_split(const float* __restrict__ f) {
    const int p = blockIdx.x * 256 + threadIdx.x;
    if (p >= NPTS) return;
    const float4* fr = (const float4*)(f + (size_t)p * 64);
    uint32_t* oh = (uint32_t*)(g_fhi + (size_t)p * 64);
    uint32_t* ol = (uint32_t*)(g_flo + (size_t)p * 64);
#pragma unroll
    for (int i = 0; i < 16; i++) {
        float4 v = fr[i];
        uint32_t h0 = pkbf(v.y, v.x), h1 = pkbf(v.w, v.z);
        float r0 = v.x - ubf_lo(h0), r1 = v.y - ubf_hi(h0);
        float r2 = v.z - ubf_lo(h1), r3 = v.w - ubf_hi(h1);
        oh[2 * i] = h0; oh[2 * i + 1] = h1;
        ol[2 * i] = pkbf(r1, r0); ol[2 * i + 1] = pkbf(r3, r2);
    }
}

// ---------------- weight prep: split + transpose + swizzle ----------------
__global__ void k_wprep(const float* __restrict__ W, int path, int cin) {
    int i = blockIdx.x * 256 + threadIdx.x;
    int total = 9 * 64 * cin;
    if (i >= total) return;
    int k = i / (64 * cin);
    int rem = i % (64 * cin);
    int n = rem / cin;
    int c = rem % cin;
    float v = W[(k * cin + c) * 64 + n];
    __nv_bfloat16 hi = __float2bfloat16(v);
    float lof = v - __bfloat162float(hi);
    unsigned off = SWZ((unsigned)(n * 128 + c * 2)) >> 1;
    g_wimg[path][k][0][off] = hi;
    g_wimg[path][k][1][off] = __float2bfloat16(lof);
}

__global__ void k_wprep2a(const float* __restrict__ W2a) {
    int i = blockIdx.x * 256 + threadIdx.x;
    if (i >= 64 * 32) return;
    int c = i >> 5, n = i & 31;          // c: input ch (K), n: output ch
    float v = W2a[c * 32 + n];
    __nv_bfloat16 hi = __float2bfloat16(v);
    float lof = v - __bfloat162float(hi);
    unsigned off = SWZ((unsigned)(n * 128 + c * 2)) >> 1;
    g_w2aimg[0][off] = hi;
    g_w2aimg[1][off] = __float2bfloat16(lof);
}

// ---------------- HMMA h = relu(bn2a(f @ W2a)), N=32, K=64, out bf16 hi/lo ----------------
__global__ __launch_bounds__(256, 2) void k_h_mma(const float* __restrict__ s,
                                                  const float* __restrict__ b) {
    extern __shared__ unsigned char smraw[];   // AH 32K | AL 32K | WH 4K | WL 4K
    const uint32_t sb = smem_u32(smraw);
    const uint32_t sAH = sb, sAL = sb + 32768, sWH = sb + 65536, sWL = sb + 69632;
    const int tid = threadIdx.x, wid = tid >> 5, lane = tid & 31;
    const int p0 = blockIdx.x * TILE;

    cpa16(sWH + tid * 16, (const char*)&g_w2aimg[0][0] + tid * 16, 16);
    cpa16(sWL + tid * 16, (const char*)&g_w2aimg[1][0] + tid * 16, 16);
    {
        const int gseg = tid & 7, grow = tid >> 3;
#pragma unroll
        for (int pass = 0; pass < 8; pass++) {
            int r = pass * 32 + grow;
            int p = p0 + r;
            uint32_t ss = (p < NPTS) ? 16u : 0u;
            int px = (p < NPTS) ? p : 0;
            uint32_t a = SWZ((unsigned)(r * 128 + gseg * 16));
            cpa16(sAH + a, g_fhi + (size_t)px * 64 + gseg * 8, ss);
            cpa16(sAL + a, g_flo + (size_t)px * 64 + gseg * 8, ss);
        }
    }
    CP_COMMIT(); CP_WAIT0();
    __syncthreads();

    float acc[2][4][4];
#pragma unroll
    for (int i = 0; i < 2; i++)
#pragma unroll
        for (int j = 0; j < 4; j++)
#pragma unroll
            for (int q = 0; q < 4; q++) acc[i][j][q] = 0.f;

    const int g = lane >> 3, lr = lane & 7;
    const int arow = (g & 1) * 8 + lr;
    const int acolb = (g >> 1) * 16;
    const int bn_ = lane & 7, bsegb = ((lane >> 3) & 1) * 16;

#pragma unroll
    for (int ks = 0; ks < 4; ks++) {
        uint32_t ah0[4], ah1[4], al0[4], al1[4];
        uint32_t ad0 = SWZ((unsigned)((wid * 32 + arow) * 128 + ks * 32 + acolb));
        uint32_t ad1 = SWZ((unsigned)((wid * 32 + 16 + arow) * 128 + ks * 32 + acolb));
        ldsm4(ah0, sAH + ad0); ldsm4(al0, sAL + ad0);
        ldsm4(ah1, sAH + ad1); ldsm4(al1, sAL + ad1);
#pragma unroll
        for (int nt = 0; nt < 4; nt++) {
            uint32_t bad = SWZ((unsigned)((nt * 8 + bn_) * 128 + ks * 32 + bsegb));
            uint32_t wh[2], wl[2];
            ldsm2(wh, sWH + bad);
            ldsm2(wl, sWL + bad);
            mma16816(acc[0][nt], ah0, wh);
            mma16816(acc[1][nt], ah1, wh);
            mma16816(acc[0][nt], al0, wh);
            mma16816(acc[1][nt], al1, wh);
            mma16816(acc[0][nt], ah0, wl);
            mma16816(acc[1][nt], ah1, wl);
        }
    }

    const int erow = lane >> 2, ecol = (lane & 3) * 2;
#pragma unroll
    for (int mt = 0; mt < 2; mt++) {
#pragma unroll
        for (int half = 0; half < 2; half++) {
            int pr = p0 + wid * 32 + mt * 16 + half * 8 + erow;
            if (pr >= NPTS) continue;
            uint32_t* oh = (uint32_t*)(g_hhi + (size_t)pr * 32);
            uint32_t* ol = (uint32_t*)(g_hlo + (size_t)pr * 32);
#pragma unroll
            for (int nt = 0; nt < 4; nt++) {
                int c = nt * 8 + ecol;
                float v0 = fmaxf(acc[mt][nt][2 * half]     * s[c]     + b[c],     0.f);
                float v1 = fmaxf(acc[mt][nt][2 * half + 1] * s[c + 1] + b[c + 1], 0.f);
                uint32_t h = pkbf(v1, v0);
                float l0 = v0 - ubf_lo(h), l1 = v1 - ubf_hi(h);
                oh[c >> 1] = h;
                ol[c >> 1] = pkbf(l1, l0);
            }
        }
    }
}

// ---------------- pipelined HMMA sparse conv path (+ fused max-pool) ----------------
// SMEM: A double buffer 2x(AH 32K + AL 32K) = 128K | W double buffer 2x(8K+8K) = 32K.
// cp.async prefetch of k+1's gather+weights overlaps k's MMA burst. 1 CTA/SM.
template <int CIN>
__global__ __launch_bounds__(256, 1) void k_path_mma(const __nv_bfloat16* __restrict__ shi,
                                                     const __nv_bfloat16* __restrict__ slo,
                                                     const int*   __restrict__ nbr,
                                                     const float* __restrict__ bns,
                                                     const float* __restrict__ bnb,
                                                     int path, int coff) {
    extern __shared__ unsigned char smraw[];
    __shared__ int cmax[64];
    const uint32_t sb = smem_u32(smraw);
    const int tid = threadIdx.x, wid = tid >> 5, lane = tid & 31;
    constexpr int NSTEP = CIN / 16;
    constexpr int SEGS = CIN / 8;
    const int p0 = blockIdx.x * TILE;
    if (tid < 64) cmax[tid] = 0;

    float acc[2][8][4];
#pragma unroll
    for (int i = 0; i < 2; i++)
#pragma unroll
        for (int j = 0; j < 8; j++)
#pragma unroll
            for (int q = 0; q < 4; q++) acc[i][j][q] = 0.f;

    const int gseg = tid & (SEGS - 1);
    const int grow = tid / SEGS;
    const int g = lane >> 3, lr = lane & 7;
    const int arow = (g & 1) * 8 + lr;
    const int acolb = (g >> 1) * 16;
    const int bn_ = lane & 7, bsegb = ((lane >> 3) & 1) * 16;

    auto issueK = [&](int k, int buf) {
        // weights (8KB hi + 8KB lo)
        {
            const char* wh = (const char*)&g_wimg[path][k][0][0];
            const char* wl = (const char*)&g_wimg[path][k][1][0];
            uint32_t dh = sb + 131072 + buf * 16384;
            uint32_t dl = dh + 8192;
            cpa16(dh + tid * 16,        wh + tid * 16,        16);
            cpa16(dh + 4096 + tid * 16, wh + 4096 + tid * 16, 16);
            cpa16(dl + tid * 16,        wl + tid * 16,        16);
            cpa16(dl + 4096 + tid * 16, wl + 4096 + tid * 16, 16);
        }
        // gather (zfill for invalid neighbors via src-size=0)
        uint32_t ab = sb + buf * 65536;
#pragma unroll
        for (int pass = 0; pass < SEGS; pass++) {
            int r = pass * (256 / SEGS) + grow;
            int p = p0 + r;
            int idx = (p < NPTS) ? __ldg(nbr + (size_t)k * NPTS + p) : -1;
            uint32_t ss = (idx >= 0) ? 16u : 0u;
            int ix = (idx >= 0) ? idx : 0;
            uint32_t a = SWZ((unsigned)(r * 128 + gseg * 16));
            cpa16(ab + a,         shi + (size_t)ix * CIN + gseg * 8, ss);
            cpa16(ab + 32768 + a, slo + (size_t)ix * CIN + gseg * 8, ss);
        }
        CP_COMMIT();
    };

    issueK(0, 0);
#pragma unroll 1
    for (int k = 0; k < 9; k++) {
        if (k < 8) { issueK(k + 1, (k + 1) & 1); CP_WAIT1(); }
        else       { CP_WAIT0(); }
        __syncthreads();
        const uint32_t sAH = sb + (k & 1) * 65536, sAL = sAH + 32768;
        const uint32_t sWH = sb + 131072 + (k & 1) * 16384, sWL = sWH + 8192;
#pragma unroll
        for (int ks = 0; ks < NSTEP; ks++) {
            uint32_t ah0[4], ah1[4], al0[4], al1[4];
            uint32_t ad0 = SWZ((unsigned)((wid * 32 + arow) * 128 + ks * 32 + acolb));
            uint32_t ad1 = SWZ((unsigned)((wid * 32 + 16 + arow) * 128 + ks * 32 + acolb));
            ldsm4(ah0, sAH + ad0); ldsm4(al0, sAL + ad0);
            ldsm4(ah1, sAH + ad1); ldsm4(al1, sAL + ad1);
#pragma unroll
            for (int nt = 0; nt < 8; nt++) {
                uint32_t bad = SWZ((unsigned)((nt * 8 + bn_) * 128 + ks * 32 + bsegb));
                uint32_t wh[2], wl[2];
                ldsm2(wh, sWH + bad);
                ldsm2(wl, sWL + bad);
                mma16816(acc[0][nt], ah0, wh);
                mma16816(acc[1][nt], ah1, wh);
                mma16816(acc[0][nt], al0, wh);
                mma16816(acc[1][nt], al1, wh);
                mma16816(acc[0][nt], ah0, wl);
                mma16816(acc[1][nt], ah1, wl);
            }
        }
        __syncthreads();   // buffer k&1 free before iteration k+1 issues k+2 into it
    }

    // epilogue: bn + relu, split to bf16 hi/lo, store ms; fused channel max
    const int erow = lane >> 2, ecol = (lane & 3) * 2;
    float tmax[8][2];
#pragma unroll
    for (int nt = 0; nt < 8; nt++) { tmax[nt][0] = 0.f; tmax[nt][1] = 0.f; }
#pragma unroll
    for (int mt = 0; mt < 2; mt++) {
#pragma unroll
        for (int half = 0; half < 2; half++) {
            int pr = p0 + wid * 32 + mt * 16 + half * 8 + erow;
            if (pr >= NPTS) continue;
            uint32_t* oh = (uint32_t*)(g_mshi + (size_t)pr * 192 + coff);
            uint32_t* ol = (uint32_t*)(g_mslo + (size_t)pr * 192 + coff);
#pragma unroll
            for (int nt = 0; nt < 8; nt++) {
                int c = nt * 8 + ecol;
                float v0 = fmaxf(acc[mt][nt][2 * half]     * bns[c]     + bnb[c],     0.f);
                float v1 = fmaxf(acc[mt][nt][2 * half + 1] * bns[c + 1] + bnb[c + 1], 0.f);
                tmax[nt][0] = fmaxf(tmax[nt][0], v0);
                tmax[nt][1] = fmaxf(tmax[nt][1], v1);
                uint32_t h = pkbf(v1, v0);
                float l0 = v0 - ubf_lo(h), l1 = v1 - ubf_hi(h);
                oh[c >> 1] = h;
                ol[c >> 1] = pkbf(l1, l0);
            }
        }
    }
    // reduce across lanes with the same channel set (stride-4 groups)
#pragma unroll
    for (int d = 16; d >= 4; d >>= 1)
#pragma unroll
        for (int nt = 0; nt < 8; nt++) {
            tmax[nt][0] = fmaxf(tmax[nt][0], __shfl_down_sync(0xffffffffu, tmax[nt][0], d));
            tmax[nt][1] = fmaxf(tmax[nt][1], __shfl_down_sync(0xffffffffu, tmax[nt][1], d));
        }
    if (lane < 4) {
#pragma unroll
        for (int nt = 0; nt < 8; nt++) {
            atomicMax(&cmax[nt * 8 + (lane & 3) * 2],     __float_as_int(tmax[nt][0]));
            atomicMax(&cmax[nt * 8 + (lane & 3) * 2 + 1], __float_as_int(tmax[nt][1]));
        }
    }
    __syncthreads();
    if (tid < 64) atomicMax((int*)&g_pooled[coff + tid], cmax[tid]);
}

// ---------------- attention MLP + fold into Wf + emit split/transposed/swizzled images ----
__global__ __launch_bounds__(192) void k_attn(const float* __restrict__ A1w,
                                              const float* __restrict__ A1b,
                                              const float* __restrict__ A2w,
                                              const float* __restrict__ A2b,
                                              const float* __restrict__ Wf) {
    __shared__ float sp[192], t1[16];
    const int t = threadIdx.x;
    sp[t] = g_pooled[t];
    __syncthreads();
    if (t < 16) {
        float s = A1b[t];
        for (int i = 0; i < 192; i++) s += sp[i] * A1w[i * 16 + t];
        t1[t] = fmaxf(s, 0.f);
    }
    __syncthreads();
    float s = A2b[t];
#pragma unroll
    for (int i = 0; i < 16; i++) s += t1[i] * A2w[i * 192 + t];
    float a = 1.f / (1.f + expf(-s));
    const int kb = t >> 6, cc = t & 63;
    for (int n = 0; n < 64; n++) {
        float v = a * Wf[t * 64 + n];
        __nv_bfloat16 hi = __float2bfloat16(v);
        float lof = v - __bfloat162float(hi);
        unsigned off = SWZ((unsigned)(n * 128 + cc * 2)) >> 1;
        g_wfimg[0][kb][off] = hi;
        g_wfimg[1][kb][off] = __float2bfloat16(lof);
    }
}

// ---------------- HMMA fusion: out = relu(bnf(ms @ Wf')) ----------------
__global__ __launch_bounds__(256, 2) void k_fuse_mma(const float* __restrict__ s,
                                                     const float* __restrict__ b,
                                                     float* __restrict__ out) {
    extern __shared__ unsigned char smraw[];
    const uint32_t sb = smem_u32(smraw);
    const uint32_t sAH = sb, sAL = sb + 32768, sWH = sb + 65536, sWL = sb + 90112;
    const int tid = threadIdx.x;
    const int wid = tid >> 5, lane = tid & 31;
    const int p0 = blockIdx.x * TILE;

    {
        const uint4* wh = (const uint4*)&g_wfimg[0][0][0];
        const uint4* wl = (const uint4*)&g_wfimg[1][0][0];
        uint4* dh = (uint4*)(smraw + 65536);
        uint4* dl = (uint4*)(smraw + 90112);
#pragma unroll
        for (int i = 0; i < 6; i++) {
            dh[i * 256 + tid] = wh[i * 256 + tid];
            dl[i * 256 + tid] = wl[i * 256 + tid];
        }
    }

    float acc[2][8][4];
#pragma unroll
    for (int i = 0; i < 2; i++)
#pragma unroll
        for (int j = 0; j < 8; j++)
#pragma unroll
            for (int q = 0; q < 4; q++) acc[i][j][q] = 0.f;

    const int gseg = tid & 7, grow = tid >> 3;
    const int g = lane >> 3, lr = lane & 7;
    const int arow = (g & 1) * 8 + lr;
    const int acolb = (g >> 1) * 16;
    const int bn_ = lane & 7, bsegb = ((lane >> 3) & 1) * 16;

#pragma unroll 1
    for (int kb = 0; kb < 3; kb++) {
        __syncthreads();
#pragma unroll
        for (int pass = 0; pass < 8; pass++) {
            int r = pass * 32 + grow;
            int p = p0 + r;
            uint32_t a = SWZ((unsigned)(r * 128 + gseg * 16));
            if (p < NPTS) {
                uint4 vh = *(const uint4*)(g_mshi + (size_t)p * 192 + kb * 64 + gseg * 8);
                uint4 vl = *(const uint4*)(g_mslo + (size_t)p * 192 + kb * 64 + gseg * 8);
                *(uint4*)(smraw + a) = vh;
                *(uint4*)(smraw + 32768 + a) = vl;
            } else {
                uint4 z = make_uint4(0, 0, 0, 0);
                *(uint4*)(smraw + a) = z;
                *(uint4*)(smraw + 32768 + a) = z;
            }
        }
        __syncthreads();
#pragma unroll
        for (int ks = 0; ks < 4; ks++) {
            uint32_t ah0[4], ah1[4], al0[4], al1[4];
            uint32_t ad0 = SWZ((unsigned)((wid * 32 + arow) * 128 + ks * 32 + acolb));
            uint32_t ad1 = SWZ((unsigned)((wid * 32 + 16 + arow) * 128 + ks * 32 + acolb));
            ldsm4(ah0, sAH + ad0); ldsm4(al0, sAL + ad0);
            ldsm4(ah1, sAH + ad1); ldsm4(al1, sAL + ad1);
#pragma unroll
            for (int nt = 0; nt < 8; nt++) {
                uint32_t bad = SWZ((unsigned)((nt * 8 + bn_) * 128 + ks * 32 + bsegb));
                uint32_t wh[2], wl[2];
                ldsm2(wh, sWH + kb * 8192 + bad);
                ldsm2(wl, sWL + kb * 8192 + bad);
                mma16816(acc[0][nt], ah0, wh);
                mma16816(acc[1][nt], ah1, wh);
                mma16816(acc[0][nt], al0, wh);
                mma16816(acc[1][nt], al1, wh);
                mma16816(acc[0][nt], ah0, wl);
                mma16816(acc[1][nt], ah1, wl);
            }
        }
    }

    const int erow = lane >> 2, ecol = (lane & 3) * 2;
#pragma unroll
    for (int mt = 0; mt < 2; mt++) {
#pragma unroll
        for (int half = 0; half < 2; half++) {
            int pr = p0 + wid * 32 + mt * 16 + half * 8 + erow;
            if (pr >= NPTS) continue;
            float* o = out + (size_t)pr * 64;
#pragma unroll
            for (int nt = 0; nt < 8; nt++) {
                int c = nt * 8 + ecol;
                float2 v;
                v.x = fmaxf(acc[mt][nt][2 * half]     * s[c]     + b[c],     0.f);
                v.y = fmaxf(acc[mt][nt][2 * half + 1] * s[c + 1] + b[c + 1], 0.f);
                *(float2*)(o + c) = v;
            }
        }
    }
}

// ---------------- launch ----------------
extern "C" void kernel_launch(void* const* d_in, const int* in_sizes, int n_in,
                              void* d_out, int out_size) {
    const float* features = (const float*)d_in[0];
    const float* W1    = (const float*)d_in[1];
    const float* bn1s  = (const float*)d_in[2];
    const float* bn1b  = (const float*)d_in[3];
    const float* W2a   = (const float*)d_in[4];
    const float* bn2as = (const float*)d_in[5];
    const float* bn2ab = (const float*)d_in[6];
    const float* W2b   = (const float*)d_in[7];
    const float* bn2bs = (const float*)d_in[8];
    const float* bn2bb = (const float*)d_in[9];
    const float* W3    = (const float*)d_in[10];
    const float* bn3s  = (const float*)d_in[11];
    const float* bn3b  = (const float*)d_in[12];
    const float* A1w   = (const float*)d_in[13];
    const float* A1b   = (const float*)d_in[14];
    const float* A2w   = (const float*)d_in[15];
    const float* A2b   = (const float*)d_in[16];
    const float* Wf    = (const float*)d_in[17];
    const float* bnfs  = (const float*)d_in[18];
    const float* bnfb  = (const float*)d_in[19];
    const int*   nbr1  = (const int*)d_in[20];
    const int*   nbr2  = (const int*)d_in[21];
    float* out = (float*)d_out;

    __nv_bfloat16 *fhi = nullptr, *flo = nullptr, *hhi = nullptr, *hlo = nullptr;
    cudaGetSymbolAddress((void**)&fhi, g_fhi);
    cudaGetSymbolAddress((void**)&flo, g_flo);
    cudaGetSymbolAddress((void**)&hhi, g_hhi);
    cudaGetSymbolAddress((void**)&hlo, g_hlo);

    const int SMEMP  = 163840;           // A 2x64K + W 2x16K
    const int SMEMH  = 73728;            // A 64K + W 8K
    const int SMEMF2 = 114688;           // AH 32K + AL 32K + WH 24K + WL 24K
    cudaFuncSetAttribute((const void*)k_path_mma<64>, cudaFuncAttributeMaxDynamicSharedMemorySize, SMEMP);
    cudaFuncSetAttribute((const void*)k_path_mma<32>, cudaFuncAttributeMaxDynamicSharedMemorySize, SMEMP);
    cudaFuncSetAttribute((const void*)k_h_mma,        cudaFuncAttributeMaxDynamicSharedMemorySize, SMEMH);
    cudaFuncSetAttribute((const void*)k_fuse_mma,     cudaFuncAttributeMaxDynamicSharedMemorySize, SMEMF2);

    k_zero<<<1, 192>>>();
    k_split<<<NBLK, 256>>>(features);
    k_wprep<<<144, 256>>>(W1, 0, 64);
    k_wprep<<<72, 256>>>(W2b, 1, 32);
    k_wprep<<<144, 256>>>(W3, 2, 64);
    k_wprep2a<<<8, 256>>>(W2a);
    k_h_mma<<<NT, 256, SMEMH>>>(bn2as, bn2ab);
    k_path_mma<64><<<NT, 256, SMEMP>>>(fhi, flo, nbr1, bn1s, bn1b, 0, 0);
    k_path_mma<32><<<NT, 256, SMEMP>>>(hhi, hlo, nbr1, bn2bs, bn2bb, 1, 64);
    k_path_mma<64><<<NT, 256, SMEMP>>>(fhi, flo, nbr2, bn3s, bn3b, 2, 128);
    k_attn<<<1, 192>>>(A1w, A1b, A2w, A2b, Wf);
    k_fuse_mma<<<NT, 256, SMEMF2>>>(bnfs, bnfb, out);
}